// round 6
// baseline (speedup 1.0000x reference)
#include <cuda_runtime.h>
#include <math.h>

// Problem constants
#define BB 32        // batch
#define CC 128       // FEAT_DIM
#define NPIX 4096    // H*W
#define SD 256       // SLOT_DIM
#define NS 8         // N_SLOTS
#define NH 4         // N_HEADS
#define HD 64        // HEAD_DIM
#define NJ 32        // NH*NS  (j = h*8 + s)
#define TILE_N 128
#define NROWS 256    // BB*NS flattened rows
#define FST 128      // featT smem row stride (XOR-swizzled chunks)
#define AST 132      // attn smem row stride (padded)
#define KT 32
#define RS (NROWS * SD)
#define LNST 260     // resident LN smem row stride

// Scratch (device globals; no allocation allowed)
__device__ float gA[BB * CC * NJ];      // per-batch folded K-projection (128x32)
__device__ float gSbias[BB * NJ];       // score bias from bk
__device__ float gM[BB * NJ * CC];      // M[b][j][c]
__device__ float gSsum[BB * NJ];        // sum_n attn[b][j]
__device__ float gAgg[RS];              // agg (GRU input x), [row][dim]
__device__ float gHid[NROWS * 2 * SD];  // MLP hidden (post-ReLU)
__device__ float gPart[6 * RS];         // gRZ[256][512] | gIN[256][256] | gHN[256][256]
__device__ int   gCnt[BB];              // per-batch completion counters

#define gRZ (gPart)
#define gIN (gPart + NROWS * 512)
#define gHN (gPart + NROWS * 512 + NROWS * 256)

// ---------------------------------------------------------------------------
// Kernel 1: LN(slots) -> q(half) -> A fold for a head-pair. grid = BB*2 = 64.
// Also zeros gM, gSsum, gCnt, and ALL of gPart.
// ---------------------------------------------------------------------------
__global__ void __launch_bounds__(256) prep_kernel(
    const float* __restrict__ slots,
    const float* __restrict__ Wq, const float* __restrict__ bq,
    const float* __restrict__ Wk, const float* __restrict__ bk,
    const float* __restrict__ g_pre, const float* __restrict__ b_pre)
{
    __shared__ float ln_s[NS][SD];
    __shared__ float qp[NS][128];
    __shared__ float q_s[NS][128];
    int b = blockIdx.x >> 1, hp = blockIdx.x & 1;
    int t = threadIdx.x;
    int w = t >> 5, lane = t & 31;

    for (int i = t; i < 16 * CC; i += 256)
        gM[b * NJ * CC + hp * 16 * CC + i] = 0.f;
    if (t < 16) gSsum[b * NJ + hp * 16 + t] = 0.f;
    if (t == 0 && hp == 0) gCnt[b] = 0;
    // zero full gPart: 6*RS floats / 64 blocks = 6144 each
    {
        float4* z = (float4*)(gPart + (size_t)blockIdx.x * 6144);
        for (int i = t; i < 1536; i += 256) z[i] = make_float4(0.f, 0.f, 0.f, 0.f);
    }

    {
        const float* row = slots + (size_t)(b * NS + w) * SD;
        float s1 = 0.f, s2 = 0.f;
        for (int k = lane; k < SD; k += 32) { float v = row[k]; s1 += v; s2 += v * v; }
        #pragma unroll
        for (int o = 16; o; o >>= 1) {
            s1 += __shfl_xor_sync(0xffffffffu, s1, o);
            s2 += __shfl_xor_sync(0xffffffffu, s2, o);
        }
        float mu = s1 * (1.f / SD);
        float var = s2 * (1.f / SD) - mu * mu;
        float rs = rsqrtf(var + 1e-5f);
        for (int k = lane; k < SD; k += 32)
            ln_s[w][k] = (row[k] - mu) * rs * g_pre[k] + b_pre[k];
    }
    __syncthreads();

    {
        int dimL = t & 127, ks = t >> 7;
        int dim = hp * 128 + dimL;
        float acc[NS];
        #pragma unroll
        for (int s = 0; s < NS; s++) acc[s] = 0.f;
        int kb = ks * 128;
        #pragma unroll 8
        for (int k = kb; k < kb + 128; k++) {
            float wv = Wq[k * SD + dim];
            #pragma unroll
            for (int s = 0; s < NS; s++) acc[s] += ln_s[s][k] * wv;
        }
        if (ks == 1) {
            #pragma unroll
            for (int s = 0; s < NS; s++) qp[s][dimL] = acc[s];
        }
        __syncthreads();
        if (ks == 0) {
            float bqv = bq[dim];
            #pragma unroll
            for (int s = 0; s < NS; s++) q_s[s][dimL] = acc[s] + qp[s][dimL] + bqv;
        }
    }
    __syncthreads();

    const float scale = 0.125f;
    for (int idx = t; idx < CC * 16; idx += 256) {
        int c = idx >> 4, jl = idx & 15;
        int hl = jl >> 3, s = jl & 7;
        const float* wk = Wk + (size_t)c * SD + (2 * hp + hl) * HD;
        const float* qq = &q_s[s][hl * HD];
        float acc = 0.f;
        #pragma unroll 8
        for (int d = 0; d < HD; d++) acc += wk[d] * qq[d];
        gA[b * CC * NJ + c * NJ + hp * 16 + jl] = acc * scale;
    }
    if (t < 16) {
        int jl = t, hl = jl >> 3, s = jl & 7;
        float acc = 0.f;
        for (int d = 0; d < HD; d++)
            acc += bk[(2 * hp + hl) * HD + d] * q_s[s][hl * HD + d];
        gSbias[b * NJ + hp * 16 + jl] = acc * scale;
    }
}

// ---------------------------------------------------------------------------
// Kernel 2 (heavy): scores + fused softmax + M partials + (last block per
// batch) the agg epilogue. grid (32, 32).
// ---------------------------------------------------------------------------
__global__ void __launch_bounds__(256) main_kernel(
    const float* __restrict__ features,
    const float* __restrict__ Wv, const float* __restrict__ bv)
{
    extern __shared__ float sm[];
    float* featT = sm;                     // [CC][FST] swizzled
    float* A_s   = featT + CC * FST;       // [CC][NJ]
    float* attn  = A_s + CC * NJ;          // [NJ][AST]
    __shared__ int sLast;

    int tile = blockIdx.x, b = blockIdx.y;
    int t = threadIdx.x;
    int n0 = tile * TILE_N;

    const float* fb = features + (size_t)b * CC * NPIX + n0;
    for (int i = t; i < CC * TILE_N / 4; i += 256) {
        int c = i >> 5, n4 = i & 31;
        int sw = (n4 ^ (c & 31)) << 2;
        *(float4*)&featT[c * FST + sw] = ((const float4*)(fb + (size_t)c * NPIX))[n4];
    }
    for (int i = t; i < CC * NJ / 4; i += 256)
        ((float4*)A_s)[i] = ((const float4*)(gA + b * CC * NJ))[i];
    __syncthreads();

    // Phase 1: scores + bias + fused softmax
    {
        int jg = t & 7, ng = t >> 3;
        int jb = jg * 4;
        float sbv[4];
        #pragma unroll
        for (int u = 0; u < 4; u++) sbv[u] = gSbias[b * NJ + jb + u];

        float acc[4][4];
        #pragma unroll
        for (int i = 0; i < 4; i++)
            #pragma unroll
            for (int u = 0; u < 4; u++) acc[i][u] = 0.f;
        #pragma unroll 4
        for (int c = 0; c < CC; c++) {
            float4 f = *(const float4*)&featT[c * FST + ((ng ^ (c & 31)) << 2)];
            float4 a = *(const float4*)&A_s[c * NJ + jb];
            float fa[4] = {f.x, f.y, f.z, f.w};
            float aa[4] = {a.x, a.y, a.z, a.w};
            #pragma unroll
            for (int i = 0; i < 4; i++)
                #pragma unroll
                for (int u = 0; u < 4; u++) acc[i][u] += fa[i] * aa[u];
        }
        #pragma unroll
        for (int i = 0; i < 4; i++)
            #pragma unroll
            for (int u = 0; u < 4; u++) acc[i][u] += sbv[u];

        #pragma unroll
        for (int i = 0; i < 4; i++) {
            float m = fmaxf(fmaxf(acc[i][0], acc[i][1]), fmaxf(acc[i][2], acc[i][3]));
            m = fmaxf(m, __shfl_xor_sync(0xffffffffu, m, 1));
            float s = 0.f;
            #pragma unroll
            for (int u = 0; u < 4; u++) { acc[i][u] = __expf(acc[i][u] - m); s += acc[i][u]; }
            s += __shfl_xor_sync(0xffffffffu, s, 1);
            float inv = 1.f / s;
            #pragma unroll
            for (int u = 0; u < 4; u++) acc[i][u] *= inv;
        }

        int nb = ng * 4;
        #pragma unroll
        for (int u = 0; u < 4; u++) {
            float4 v = make_float4(acc[0][u], acc[1][u], acc[2][u], acc[3][u]);
            *(float4*)&attn[(jb + u) * AST + nb] = v;
        }

        float p[4];
        #pragma unroll
        for (int u = 0; u < 4; u++)
            p[u] = acc[0][u] + acc[1][u] + acc[2][u] + acc[3][u];
        #pragma unroll
        for (int u = 0; u < 4; u++) {
            p[u] += __shfl_xor_sync(0xffffffffu, p[u], 8);
            p[u] += __shfl_xor_sync(0xffffffffu, p[u], 16);
        }
        if ((t & 31) < 8) {
            #pragma unroll
            for (int u = 0; u < 4; u++) atomicAdd(&gSsum[b * NJ + jb + u], p[u]);
        }
    }
    __syncthreads();

    // Phase 3: M partials
    {
        int jb = (t >> 5) * 4, cg = t & 31;
        float acc[4][4];
        #pragma unroll
        for (int u = 0; u < 4; u++)
            #pragma unroll
            for (int r = 0; r < 4; r++) acc[u][r] = 0.f;
        for (int nn = 0; nn < TILE_N; nn += 4) {
            float4 av[4];
            #pragma unroll
            for (int u = 0; u < 4; u++)
                av[u] = *(const float4*)&attn[(jb + u) * AST + nn];
            int swc = ((nn >> 2) ^ cg) << 2;
            #pragma unroll
            for (int r = 0; r < 4; r++) {
                float4 fv = *(const float4*)&featT[(cg + 32 * r) * FST + swc];
                #pragma unroll
                for (int u = 0; u < 4; u++)
                    acc[u][r] += av[u].x * fv.x + av[u].y * fv.y
                               + av[u].z * fv.z + av[u].w * fv.w;
            }
        }
        float* gm = gM + b * NJ * CC;
        #pragma unroll
        for (int u = 0; u < 4; u++)
            #pragma unroll
            for (int r = 0; r < 4; r++)
                atomicAdd(&gm[(jb + u) * CC + cg + 32 * r], acc[u][r]);
    }

    // ---- last-block-per-batch agg epilogue -------------------------------
    __threadfence();
    __syncthreads();
    if (t == 0) {
        int old = atomicAdd(&gCnt[b], 1);
        sLast = (old == 31);
    }
    __syncthreads();
    if (!sLast) return;
    __threadfence();

    // agg[b*8+s][dim] = sum_c M[b][h*8+s][c]*Wv[c][dim] + Ssum*bv[dim]
    float* Ms = sm;     // reuse: [NS][CC]
    {
        int s = t >> 5, c4 = t & 31;
        ((float4*)&Ms[s * CC])[c4] =
            __ldcg((const float4*)(gM + (size_t)b * NJ * CC + ((c4 & 3) * 0 + s) * 0 + 0) + 0); // placeholder avoided below
    }
    // (re-do staging properly: j rows are h*8+s; we stage all 32 j rows? No:
    // agg needs, for dim's head h, row j=h*8+s. Stage full gM[b]: 32x128.)
    __syncthreads();
    {
        // stage full 32x128 M block (16KB) into sm
        for (int i = t; i < NJ * CC / 4; i += 256)
            ((float4*)sm)[i] = __ldcg(((const float4*)(gM + (size_t)b * NJ * CC)) + i);
    }
    __shared__ float ssum_s[NJ];
    if (t < NJ) ssum_s[t] = __ldcg(&gSsum[b * NJ + t]);
    __syncthreads();

    {
        int dim = t;                 // 0..255
        int h = dim >> 6;
        float acc[NS];
        #pragma unroll
        for (int s = 0; s < NS; s++) acc[s] = ssum_s[h * 8 + s] * bv[dim];
        #pragma unroll 4
        for (int c = 0; c < CC; c++) {
            float wv = __ldg(&Wv[(size_t)c * SD + dim]);
            #pragma unroll
            for (int s = 0; s < NS; s++) acc[s] += sm[(h * 8 + s) * CC + c] * wv;
        }
        #pragma unroll
        for (int s = 0; s < NS; s++)
            gAgg[(size_t)(b * NS + s) * SD + dim] = acc[s];
    }
}

// ---------------------------------------------------------------------------
// Kernel 3: GRU gate GEMM. Tile 64m x 32d x 3 gates, K-split 4, phase-split 2.
// grid (4, 8, 8) = 256 blocks. Atomic into zero-primed gPart.
// ---------------------------------------------------------------------------
__global__ void __launch_bounds__(256) gru_kernel(
    const float* __restrict__ slots,
    const float* __restrict__ W_ih, const float* __restrict__ W_hh)
{
    __shared__ float As[64][KT + 1];
    __shared__ float Bs[3][32][KT + 1];
    int m0 = blockIdx.x * 64, dim0 = blockIdx.y * 32;
    int phase = blockIdx.z >> 2, kq = blockIdx.z & 3;
    int t = threadIdx.x;
    int di = t & 15, mi = t >> 4;

    float accg[3][4][2];
    #pragma unroll
    for (int g = 0; g < 3; g++)
        #pragma unroll
        for (int i = 0; i < 4; i++)
            #pragma unroll
            for (int j = 0; j < 2; j++) accg[g][i][j] = 0.f;

    int lk = t & 7;
    const float* Ag = phase ? slots : gAgg;
    const float* Wg = phase ? W_hh : W_ih;
    int kbase = kq * 64;

    for (int k0 = kbase; k0 < kbase + 64; k0 += KT) {
        #pragma unroll
        for (int rep = 0; rep < 2; rep++) {
            int idx = t + rep * 256;
            int row = idx >> 3;
            float4 v = *(const float4*)(Ag + (size_t)(m0 + row) * SD + k0 + lk * 4);
            As[row][lk * 4 + 0] = v.x; As[row][lk * 4 + 1] = v.y;
            As[row][lk * 4 + 2] = v.z; As[row][lk * 4 + 3] = v.w;
        }
        {
            int lm = t >> 3;
            #pragma unroll
            for (int g = 0; g < 3; g++) {
                float4 v = *(const float4*)(Wg + (size_t)(g * SD + dim0 + lm) * SD + k0 + lk * 4);
                Bs[g][lm][lk * 4 + 0] = v.x; Bs[g][lm][lk * 4 + 1] = v.y;
                Bs[g][lm][lk * 4 + 2] = v.z; Bs[g][lm][lk * 4 + 3] = v.w;
            }
        }
        __syncthreads();
        #pragma unroll 4
        for (int k = 0; k < KT; k++) {
            float a[4];
            #pragma unroll
            for (int i = 0; i < 4; i++) a[i] = As[mi * 4 + i][k];
            #pragma unroll
            for (int g = 0; g < 3; g++) {
                float b0 = Bs[g][di * 2 + 0][k];
                float b1 = Bs[g][di * 2 + 1][k];
                #pragma unroll
                for (int i = 0; i < 4; i++) {
                    accg[g][i][0] += a[i] * b0;
                    accg[g][i][1] += a[i] * b1;
                }
            }
        }
        __syncthreads();
    }

    float* dstN = phase ? gHN : gIN;
    #pragma unroll
    for (int i = 0; i < 4; i++) {
        int m = m0 + mi * 4 + i;
        #pragma unroll
        for (int j = 0; j < 2; j++) {
            int d = dim0 + di * 2 + j;
            atomicAdd(&gRZ[(size_t)m * 512 + d], accg[0][i][j]);
            atomicAdd(&gRZ[(size_t)m * 512 + 256 + d], accg[1][i][j]);
            atomicAdd(&dstN[(size_t)m * SD + d], accg[2][i][j]);
        }
    }
}

// ---------------------------------------------------------------------------
// Kernel 4: fused GRU-finalize + post-LN (in smem) + mlp1 GEMM.
// grid (8 m-tiles, 8 n-tiles). blockIdx.y==0 blocks also prime out = upd + b2.
// ---------------------------------------------------------------------------
__global__ void __launch_bounds__(256) mlp1_kernel(
    const float* __restrict__ slots,
    const float* __restrict__ b_ih, const float* __restrict__ b_hh,
    const float* __restrict__ g_post, const float* __restrict__ b_post,
    const float* __restrict__ W1, const float* __restrict__ b1,
    const float* __restrict__ b2, float* __restrict__ out)
{
    __shared__ float LNs[32][LNST];      // resident A operand (post-LN rows)
    __shared__ float Bs[KT][68];
    int m0 = blockIdx.x * 32, n0 = blockIdx.y * 64;
    int t = threadIdx.x;
    int w = t >> 5, lane = t & 31;

    // finalize + LN for rows m0..m0+31 (warp w handles rows w*4..w*4+3)
    #pragma unroll
    for (int rr = 0; rr < 4; rr++) {
        int rloc = w * 4 + rr;
        int row = m0 + rloc;
        size_t ro = (size_t)row * SD;
        float vals[8];
        float s1 = 0.f, s2 = 0.f;
        #pragma unroll
        for (int r8 = 0; r8 < 8; r8++) {
            int d = r8 * 32 + lane;
            float rz_r = gRZ[(size_t)row * 512 + d] + b_ih[d] + b_hh[d];
            float rz_z = gRZ[(size_t)row * 512 + 256 + d] + b_ih[SD + d] + b_hh[SD + d];
            float in_ = gIN[ro + d] + b_ih[2 * SD + d];
            float hn = gHN[ro + d] + b_hh[2 * SD + d];
            float r = 1.f / (1.f + expf(-rz_r));
            float z = 1.f / (1.f + expf(-rz_z));
            float nn = tanhf(in_ + r * hn);
            float hp = slots[ro + d];
            float v = (1.f - z) * nn + z * hp;
            if (blockIdx.y == 0) out[ro + d] = v + b2[d];
            vals[r8] = v;
            s1 += v; s2 += v * v;
        }
        #pragma unroll
        for (int o = 16; o; o >>= 1) {
            s1 += __shfl_xor_sync(0xffffffffu, s1, o);
            s2 += __shfl_xor_sync(0xffffffffu, s2, o);
        }
        float mu = s1 * (1.f / SD);
        float var = s2 * (1.f / SD) - mu * mu;
        float rs = rsqrtf(var + 1e-5f);
        #pragma unroll
        for (int r8 = 0; r8 < 8; r8++) {
            int d = r8 * 32 + lane;
            LNs[rloc][d] = (vals[r8] - mu) * rs * g_post[d] + b_post[d];
        }
    }
    __syncthreads();

    // GEMM: gHid[m][n] = relu(LNs @ W1 + b1), tile 32x64, K=256
    int ni = t & 15, mi = t >> 4;
    float acc[2][4] = {{0,0,0,0},{0,0,0,0}};
    for (int k0 = 0; k0 < SD; k0 += KT) {
        #pragma unroll
        for (int rep = 0; rep < 2; rep++) {
            int i = t + rep * 256;
            int k = i >> 4, nc = i & 15;
            float4 v = *(const float4*)(W1 + (size_t)(k0 + k) * (2 * SD) + n0 + nc * 4);
            *(float4*)&Bs[k][nc * 4] = v;
        }
        __syncthreads();
        #pragma unroll 8
        for (int k = 0; k < KT; k++) {
            float a0 = LNs[mi * 2 + 0][k0 + k], a1 = LNs[mi * 2 + 1][k0 + k];
            float4 bv4 = *(const float4*)&Bs[k][ni * 4];
            acc[0][0] += a0 * bv4.x; acc[0][1] += a0 * bv4.y;
            acc[0][2] += a0 * bv4.z; acc[0][3] += a0 * bv4.w;
            acc[1][0] += a1 * bv4.x; acc[1][1] += a1 * bv4.y;
            acc[1][2] += a1 * bv4.z; acc[1][3] += a1 * bv4.w;
        }
        __syncthreads();
    }
    #pragma unroll
    for (int ii = 0; ii < 2; ii++) {
        int m = m0 + mi * 2 + ii;
        #pragma unroll
        for (int u = 0; u < 4; u++) {
            int n = n0 + ni * 4 + u;
            gHid[(size_t)m * (2 * SD) + n] = fmaxf(acc[ii][u] + b1[n], 0.f);
        }
    }
}

// ---------------------------------------------------------------------------
// Kernel 5: out += gHid @ W2, K-split 2 (atomic into primed out).
// Grid (16, 4, 2), tile 16m x 64n x K256.
// ---------------------------------------------------------------------------
__global__ void __launch_bounds__(256) mlp2_kernel(
    const float* __restrict__ W2, float* __restrict__ out)
{
    __shared__ float As[16][KT + 1];
    __shared__ float Bs[KT][68];
    int m0 = blockIdx.x * 16, n0 = blockIdx.y * 64;
    int kbase = blockIdx.z * 256;
    int t = threadIdx.x;
    int ni = t & 15, mi = t >> 4;
    float acc[4] = {0, 0, 0, 0};

    for (int k0 = kbase; k0 < kbase + 256; k0 += KT) {
        if (t < 128) {
            int lm = t >> 3, lk = t & 7;
            float4 v = *(const float4*)(gHid + (size_t)(m0 + lm) * (2 * SD) + k0 + lk * 4);
            As[lm][lk * 4 + 0] = v.x; As[lm][lk * 4 + 1] = v.y;
            As[lm][lk * 4 + 2] = v.z; As[lm][lk * 4 + 3] = v.w;
        }
        #pragma unroll
        for (int rep = 0; rep < 2; rep++) {
            int i = t + rep * 256;
            int k = i >> 4, nc = i & 15;
            float4 v = *(const float4*)(W2 + (size_t)(k0 + k) * SD + n0 + nc * 4);
            *(float4*)&Bs[k][nc * 4] = v;
        }
        __syncthreads();
        #pragma unroll 8
        for (int k = 0; k < KT; k++) {
            float a = As[mi][k];
            float4 bv4 = *(const float4*)&Bs[k][ni * 4];
            acc[0] += a * bv4.x; acc[1] += a * bv4.y;
            acc[2] += a * bv4.z; acc[3] += a * bv4.w;
        }
        __syncthreads();
    }
    int m = m0 + mi;
    #pragma unroll
    for (int u = 0; u < 4; u++) {
        int n = n0 + ni * 4 + u;
        atomicAdd(&out[(size_t)m * SD + n], acc[u]);
    }
}

// ---------------------------------------------------------------------------
extern "C" void kernel_launch(void* const* d_in, const int* in_sizes, int n_in,
                              void* d_out, int out_size)
{
    const float* features = (const float*)d_in[0];
    const float* slots    = (const float*)d_in[1];
    const float* Wq   = (const float*)d_in[2];
    const float* bq   = (const float*)d_in[3];
    const float* Wk   = (const float*)d_in[4];
    const float* bk   = (const float*)d_in[5];
    const float* Wv   = (const float*)d_in[6];
    const float* bv   = (const float*)d_in[7];
    const float* W_ih = (const float*)d_in[8];
    const float* b_ih = (const float*)d_in[9];
    const float* W_hh = (const float*)d_in[10];
    const float* b_hh = (const float*)d_in[11];
    const float* g_pre  = (const float*)d_in[12];
    const float* b_pre  = (const float*)d_in[13];
    const float* g_post = (const float*)d_in[14];
    const float* b_post = (const float*)d_in[15];
    const float* W1 = (const float*)d_in[16];
    const float* b1 = (const float*)d_in[17];
    const float* W2 = (const float*)d_in[18];
    const float* b2 = (const float*)d_in[19];
    float* out = (float*)d_out;

    prep_kernel<<<BB * 2, 256>>>(slots, Wq, bq, Wk, bk, g_pre, b_pre);

    size_t smem = (size_t)(CC * FST + CC * NJ + NJ * AST) * sizeof(float);
    cudaFuncSetAttribute(main_kernel, cudaFuncAttributeMaxDynamicSharedMemorySize, (int)smem);
    main_kernel<<<dim3(NPIX / TILE_N, BB), 256, smem>>>(features, Wv, bv);

    gru_kernel<<<dim3(NROWS / 64, SD / 32, 8), 256>>>(slots, W_ih, W_hh);
    mlp1_kernel<<<dim3(NROWS / 32, (2 * SD) / 64), 256>>>(
        slots, b_ih, b_hh, g_post, b_post, W1, b1, b2, out);
    mlp2_kernel<<<dim3(NROWS / 16, SD / 64, 2), 256>>>(W2, out);
}

// round 7
// speedup vs baseline: 1.0483x; 1.0483x over previous
#include <cuda_runtime.h>
#include <math.h>

// Problem constants
#define BB 32        // batch
#define CC 128       // FEAT_DIM
#define NPIX 4096    // H*W
#define SD 256       // SLOT_DIM
#define NS 8         // N_SLOTS
#define NH 4         // N_HEADS
#define HD 64        // HEAD_DIM
#define NJ 32        // NH*NS  (j = h*8 + s)
#define TILE_N 128
#define NROWS 256    // BB*NS flattened rows
#define FST 128      // featT smem row stride (XOR-swizzled chunks)
#define AST 132      // attn smem row stride (padded)
#define KT 32
#define RS (NROWS * SD)

// Scratch (device globals; no allocation allowed)
__device__ float gA[BB * CC * NJ];      // per-batch folded K-projection (128x32)
__device__ float gSbias[BB * NJ];       // score bias from bk
__device__ float gM[BB * NJ * CC];      // M[b][j][c]
__device__ float gSsum[BB * NJ];        // sum_n attn[b][j]
__device__ float gAgg[RS];              // agg (GRU input x), [row][dim]
__device__ float gLN[RS];               // post-LN of updated
__device__ float gHid[NROWS * 2 * SD];  // MLP hidden (post-ReLU)
__device__ float gPart[6 * RS];         // gRZ[256][512] | gIN[256][256] | gHN[256][256]
__device__ int   gCnt[BB];              // per-batch completion counters

#define gRZ (gPart)
#define gIN (gPart + NROWS * 512)
#define gHN (gPart + NROWS * 512 + NROWS * 256)

// ---------------------------------------------------------------------------
// Kernel 1: LN(slots) -> q(half) -> A fold for a head-pair. grid = BB*2 = 64.
// Also zeros gM, gSsum, gCnt, and ALL of gPart.
// ---------------------------------------------------------------------------
__global__ void __launch_bounds__(256) prep_kernel(
    const float* __restrict__ slots,
    const float* __restrict__ Wq, const float* __restrict__ bq,
    const float* __restrict__ Wk, const float* __restrict__ bk,
    const float* __restrict__ g_pre, const float* __restrict__ b_pre)
{
    __shared__ float ln_s[NS][SD];
    __shared__ float qp[NS][128];
    __shared__ float q_s[NS][128];
    int b = blockIdx.x >> 1, hp = blockIdx.x & 1;
    int t = threadIdx.x;
    int w = t >> 5, lane = t & 31;

    for (int i = t; i < 16 * CC; i += 256)
        gM[b * NJ * CC + hp * 16 * CC + i] = 0.f;
    if (t < 16) gSsum[b * NJ + hp * 16 + t] = 0.f;
    if (t == 0 && hp == 0) gCnt[b] = 0;
    // zero full gPart: 6*RS floats / 64 blocks = 6144 each
    {
        float4* z = (float4*)(gPart + (size_t)blockIdx.x * 6144);
        for (int i = t; i < 1536; i += 256) z[i] = make_float4(0.f, 0.f, 0.f, 0.f);
    }

    {
        const float* row = slots + (size_t)(b * NS + w) * SD;
        float s1 = 0.f, s2 = 0.f;
        for (int k = lane; k < SD; k += 32) { float v = row[k]; s1 += v; s2 += v * v; }
        #pragma unroll
        for (int o = 16; o; o >>= 1) {
            s1 += __shfl_xor_sync(0xffffffffu, s1, o);
            s2 += __shfl_xor_sync(0xffffffffu, s2, o);
        }
        float mu = s1 * (1.f / SD);
        float var = s2 * (1.f / SD) - mu * mu;
        float rs = rsqrtf(var + 1e-5f);
        for (int k = lane; k < SD; k += 32)
            ln_s[w][k] = (row[k] - mu) * rs * g_pre[k] + b_pre[k];
    }
    __syncthreads();

    {
        int dimL = t & 127, ks = t >> 7;
        int dim = hp * 128 + dimL;
        float acc[NS];
        #pragma unroll
        for (int s = 0; s < NS; s++) acc[s] = 0.f;
        int kb = ks * 128;
        #pragma unroll 8
        for (int k = kb; k < kb + 128; k++) {
            float wv = Wq[k * SD + dim];
            #pragma unroll
            for (int s = 0; s < NS; s++) acc[s] += ln_s[s][k] * wv;
        }
        if (ks == 1) {
            #pragma unroll
            for (int s = 0; s < NS; s++) qp[s][dimL] = acc[s];
        }
        __syncthreads();
        if (ks == 0) {
            float bqv = bq[dim];
            #pragma unroll
            for (int s = 0; s < NS; s++) q_s[s][dimL] = acc[s] + qp[s][dimL] + bqv;
        }
    }
    __syncthreads();

    const float scale = 0.125f;
    for (int idx = t; idx < CC * 16; idx += 256) {
        int c = idx >> 4, jl = idx & 15;
        int hl = jl >> 3, s = jl & 7;
        const float* wk = Wk + (size_t)c * SD + (2 * hp + hl) * HD;
        const float* qq = &q_s[s][hl * HD];
        float acc = 0.f;
        #pragma unroll 8
        for (int d = 0; d < HD; d++) acc += wk[d] * qq[d];
        gA[b * CC * NJ + c * NJ + hp * 16 + jl] = acc * scale;
    }
    if (t < 16) {
        int jl = t, hl = jl >> 3, s = jl & 7;
        float acc = 0.f;
        for (int d = 0; d < HD; d++)
            acc += bk[(2 * hp + hl) * HD + d] * q_s[s][hl * HD + d];
        gSbias[b * NJ + hp * 16 + jl] = acc * scale;
    }
}

// ---------------------------------------------------------------------------
// Kernel 2 (heavy): scores + fused softmax + M partials + (last block per
// batch) the agg epilogue. grid (32, 32).
// ---------------------------------------------------------------------------
__global__ void __launch_bounds__(256) main_kernel(
    const float* __restrict__ features,
    const float* __restrict__ Wv, const float* __restrict__ bv)
{
    extern __shared__ float sm[];
    float* featT = sm;                     // [CC][FST] swizzled
    float* A_s   = featT + CC * FST;       // [CC][NJ]
    float* attn  = A_s + CC * NJ;          // [NJ][AST]
    __shared__ int sLast;

    int tile = blockIdx.x, b = blockIdx.y;
    int t = threadIdx.x;
    int n0 = tile * TILE_N;

    const float* fb = features + (size_t)b * CC * NPIX + n0;
    for (int i = t; i < CC * TILE_N / 4; i += 256) {
        int c = i >> 5, n4 = i & 31;
        int sw = (n4 ^ (c & 31)) << 2;
        *(float4*)&featT[c * FST + sw] = ((const float4*)(fb + (size_t)c * NPIX))[n4];
    }
    for (int i = t; i < CC * NJ / 4; i += 256)
        ((float4*)A_s)[i] = ((const float4*)(gA + b * CC * NJ))[i];
    __syncthreads();

    // Phase 1: scores + bias + fused softmax
    {
        int jg = t & 7, ng = t >> 3;
        int jb = jg * 4;
        float sbv[4];
        #pragma unroll
        for (int u = 0; u < 4; u++) sbv[u] = gSbias[b * NJ + jb + u];

        float acc[4][4];
        #pragma unroll
        for (int i = 0; i < 4; i++)
            #pragma unroll
            for (int u = 0; u < 4; u++) acc[i][u] = 0.f;
        #pragma unroll 4
        for (int c = 0; c < CC; c++) {
            float4 f = *(const float4*)&featT[c * FST + ((ng ^ (c & 31)) << 2)];
            float4 a = *(const float4*)&A_s[c * NJ + jb];
            float fa[4] = {f.x, f.y, f.z, f.w};
            float aa[4] = {a.x, a.y, a.z, a.w};
            #pragma unroll
            for (int i = 0; i < 4; i++)
                #pragma unroll
                for (int u = 0; u < 4; u++) acc[i][u] += fa[i] * aa[u];
        }
        #pragma unroll
        for (int i = 0; i < 4; i++)
            #pragma unroll
            for (int u = 0; u < 4; u++) acc[i][u] += sbv[u];

        #pragma unroll
        for (int i = 0; i < 4; i++) {
            float m = fmaxf(fmaxf(acc[i][0], acc[i][1]), fmaxf(acc[i][2], acc[i][3]));
            m = fmaxf(m, __shfl_xor_sync(0xffffffffu, m, 1));
            float s = 0.f;
            #pragma unroll
            for (int u = 0; u < 4; u++) { acc[i][u] = __expf(acc[i][u] - m); s += acc[i][u]; }
            s += __shfl_xor_sync(0xffffffffu, s, 1);
            float inv = 1.f / s;
            #pragma unroll
            for (int u = 0; u < 4; u++) acc[i][u] *= inv;
        }

        int nb = ng * 4;
        #pragma unroll
        for (int u = 0; u < 4; u++) {
            float4 v = make_float4(acc[0][u], acc[1][u], acc[2][u], acc[3][u]);
            *(float4*)&attn[(jb + u) * AST + nb] = v;
        }

        float p[4];
        #pragma unroll
        for (int u = 0; u < 4; u++)
            p[u] = acc[0][u] + acc[1][u] + acc[2][u] + acc[3][u];
        #pragma unroll
        for (int u = 0; u < 4; u++) {
            p[u] += __shfl_xor_sync(0xffffffffu, p[u], 8);
            p[u] += __shfl_xor_sync(0xffffffffu, p[u], 16);
        }
        if ((t & 31) < 8) {
            #pragma unroll
            for (int u = 0; u < 4; u++) atomicAdd(&gSsum[b * NJ + jb + u], p[u]);
        }
    }
    __syncthreads();

    // Phase 3: M partials
    {
        int jb = (t >> 5) * 4, cg = t & 31;
        float acc[4][4];
        #pragma unroll
        for (int u = 0; u < 4; u++)
            #pragma unroll
            for (int r = 0; r < 4; r++) acc[u][r] = 0.f;
        for (int nn = 0; nn < TILE_N; nn += 4) {
            float4 av[4];
            #pragma unroll
            for (int u = 0; u < 4; u++)
                av[u] = *(const float4*)&attn[(jb + u) * AST + nn];
            int swc = ((nn >> 2) ^ cg) << 2;
            #pragma unroll
            for (int r = 0; r < 4; r++) {
                float4 fv = *(const float4*)&featT[(cg + 32 * r) * FST + swc];
                #pragma unroll
                for (int u = 0; u < 4; u++)
                    acc[u][r] += av[u].x * fv.x + av[u].y * fv.y
                               + av[u].z * fv.z + av[u].w * fv.w;
            }
        }
        float* gm = gM + b * NJ * CC;
        #pragma unroll
        for (int u = 0; u < 4; u++)
            #pragma unroll
            for (int r = 0; r < 4; r++)
                atomicAdd(&gm[(jb + u) * CC + cg + 32 * r], acc[u][r]);
    }

    // ---- last-block-per-batch agg epilogue -------------------------------
    __threadfence();
    __syncthreads();
    if (t == 0) {
        int old = atomicAdd(&gCnt[b], 1);
        sLast = (old == 31);
    }
    __syncthreads();
    if (!sLast) return;
    __threadfence();

    // stage full 32x128 M block (16KB) into smem (L2 reads; atomics are L2)
    for (int i = t; i < NJ * CC / 4; i += 256)
        ((float4*)sm)[i] = __ldcg(((const float4*)(gM + (size_t)b * NJ * CC)) + i);
    __shared__ float ssum_s[NJ];
    if (t < NJ) ssum_s[t] = __ldcg(&gSsum[b * NJ + t]);
    __syncthreads();

    // agg[b*8+s][dim] = sum_c M[b][h*8+s][c]*Wv[c][dim] + Ssum*bv[dim]
    {
        int dim = t;                 // 0..255
        int h = dim >> 6;
        float acc[NS];
        #pragma unroll
        for (int s = 0; s < NS; s++) acc[s] = ssum_s[h * 8 + s] * bv[dim];
        #pragma unroll 4
        for (int c = 0; c < CC; c++) {
            float wv = __ldg(&Wv[(size_t)c * SD + dim]);
            #pragma unroll
            for (int s = 0; s < NS; s++) acc[s] += sm[(h * 8 + s) * CC + c] * wv;
        }
        #pragma unroll
        for (int s = 0; s < NS; s++)
            gAgg[(size_t)(b * NS + s) * SD + dim] = acc[s];
    }
}

// ---------------------------------------------------------------------------
// Kernel 3: GRU gate GEMM. Tile 64m x 32d x 3 gates, K-split 4, phase-split 2.
// grid (4, 8, 8) = 256 blocks. Atomic into zero-primed gPart.
// ---------------------------------------------------------------------------
__global__ void __launch_bounds__(256) gru_kernel(
    const float* __restrict__ slots,
    const float* __restrict__ W_ih, const float* __restrict__ W_hh)
{
    __shared__ float As[64][KT + 1];
    __shared__ float Bs[3][32][KT + 1];
    int m0 = blockIdx.x * 64, dim0 = blockIdx.y * 32;
    int phase = blockIdx.z >> 2, kq = blockIdx.z & 3;
    int t = threadIdx.x;
    int di = t & 15, mi = t >> 4;

    float accg[3][4][2];
    #pragma unroll
    for (int g = 0; g < 3; g++)
        #pragma unroll
        for (int i = 0; i < 4; i++)
            #pragma unroll
            for (int j = 0; j < 2; j++) accg[g][i][j] = 0.f;

    int lk = t & 7;
    const float* Ag = phase ? slots : gAgg;
    const float* Wg = phase ? W_hh : W_ih;
    int kbase = kq * 64;

    for (int k0 = kbase; k0 < kbase + 64; k0 += KT) {
        #pragma unroll
        for (int rep = 0; rep < 2; rep++) {
            int idx = t + rep * 256;
            int row = idx >> 3;
            float4 v = *(const float4*)(Ag + (size_t)(m0 + row) * SD + k0 + lk * 4);
            As[row][lk * 4 + 0] = v.x; As[row][lk * 4 + 1] = v.y;
            As[row][lk * 4 + 2] = v.z; As[row][lk * 4 + 3] = v.w;
        }
        {
            int lm = t >> 3;
            #pragma unroll
            for (int g = 0; g < 3; g++) {
                float4 v = *(const float4*)(Wg + (size_t)(g * SD + dim0 + lm) * SD + k0 + lk * 4);
                Bs[g][lm][lk * 4 + 0] = v.x; Bs[g][lm][lk * 4 + 1] = v.y;
                Bs[g][lm][lk * 4 + 2] = v.z; Bs[g][lm][lk * 4 + 3] = v.w;
            }
        }
        __syncthreads();
        #pragma unroll 4
        for (int k = 0; k < KT; k++) {
            float a[4];
            #pragma unroll
            for (int i = 0; i < 4; i++) a[i] = As[mi * 4 + i][k];
            #pragma unroll
            for (int g = 0; g < 3; g++) {
                float b0 = Bs[g][di * 2 + 0][k];
                float b1 = Bs[g][di * 2 + 1][k];
                #pragma unroll
                for (int i = 0; i < 4; i++) {
                    accg[g][i][0] += a[i] * b0;
                    accg[g][i][1] += a[i] * b1;
                }
            }
        }
        __syncthreads();
    }

    float* dstN = phase ? gHN : gIN;
    #pragma unroll
    for (int i = 0; i < 4; i++) {
        int m = m0 + mi * 4 + i;
        #pragma unroll
        for (int j = 0; j < 2; j++) {
            int d = dim0 + di * 2 + j;
            atomicAdd(&gRZ[(size_t)m * 512 + d], accg[0][i][j]);
            atomicAdd(&gRZ[(size_t)m * 512 + 256 + d], accg[1][i][j]);
            atomicAdd(&dstN[(size_t)m * SD + d], accg[2][i][j]);
        }
    }
}

// ---------------------------------------------------------------------------
// Kernel 4: GRU nonlin + post-LN + prime out = upd + b2. grid 32, warp/row.
// ---------------------------------------------------------------------------
__global__ void __launch_bounds__(256) fin_kernel(
    const float* __restrict__ slots,
    const float* __restrict__ b_ih, const float* __restrict__ b_hh,
    const float* __restrict__ g_post, const float* __restrict__ b_post,
    const float* __restrict__ b2, float* __restrict__ out)
{
    int row = blockIdx.x * 8 + (threadIdx.x >> 5);
    int lane = threadIdx.x & 31;
    float vals[8];
    float s1 = 0.f, s2 = 0.f;
    size_t ro = (size_t)row * SD;
    #pragma unroll
    for (int r8 = 0; r8 < 8; r8++) {
        int d = r8 * 32 + lane;
        float rz_r = gRZ[(size_t)row * 512 + d] + b_ih[d] + b_hh[d];
        float rz_z = gRZ[(size_t)row * 512 + 256 + d] + b_ih[SD + d] + b_hh[SD + d];
        float in_ = gIN[ro + d] + b_ih[2 * SD + d];
        float hn = gHN[ro + d] + b_hh[2 * SD + d];
        float r = 1.f / (1.f + expf(-rz_r));
        float z = 1.f / (1.f + expf(-rz_z));
        float nn = tanhf(in_ + r * hn);
        float hp = slots[ro + d];
        float v = (1.f - z) * nn + z * hp;
        out[ro + d] = v + b2[d];
        vals[r8] = v;
        s1 += v; s2 += v * v;
    }
    #pragma unroll
    for (int o = 16; o; o >>= 1) {
        s1 += __shfl_xor_sync(0xffffffffu, s1, o);
        s2 += __shfl_xor_sync(0xffffffffu, s2, o);
    }
    float mu = s1 * (1.f / SD);
    float var = s2 * (1.f / SD) - mu * mu;
    float rs = rsqrtf(var + 1e-5f);
    #pragma unroll
    for (int r8 = 0; r8 < 8; r8++) {
        int d = r8 * 32 + lane;
        gLN[ro + d] = (vals[r8] - mu) * rs * g_post[d] + b_post[d];
    }
}

// ---------------------------------------------------------------------------
// Kernel 5: gHid = relu(gLN @ W1 + b1). Grid (8, 8), tile 32x64.
// ---------------------------------------------------------------------------
__global__ void __launch_bounds__(256) mlp1_kernel(
    const float* __restrict__ W1, const float* __restrict__ b1)
{
    __shared__ float As[32][KT + 1];
    __shared__ float Bs[KT][68];
    int m0 = blockIdx.x * 32, n0 = blockIdx.y * 64;
    int t = threadIdx.x;
    int ni = t & 15, mi = t >> 4;
    float acc[2][4] = {{0,0,0,0},{0,0,0,0}};
    int lm = t >> 3, lk = t & 7;

    for (int k0 = 0; k0 < SD; k0 += KT) {
        {
            float4 v = *(const float4*)(gLN + (size_t)(m0 + lm) * SD + k0 + lk * 4);
            As[lm][lk * 4 + 0] = v.x; As[lm][lk * 4 + 1] = v.y;
            As[lm][lk * 4 + 2] = v.z; As[lm][lk * 4 + 3] = v.w;
        }
        #pragma unroll
        for (int rep = 0; rep < 2; rep++) {
            int i = t + rep * 256;
            int k = i >> 4, nc = i & 15;
            float4 v = *(const float4*)(W1 + (size_t)(k0 + k) * (2 * SD) + n0 + nc * 4);
            *(float4*)&Bs[k][nc * 4] = v;
        }
        __syncthreads();
        #pragma unroll 8
        for (int k = 0; k < KT; k++) {
            float a0 = As[mi * 2 + 0][k], a1 = As[mi * 2 + 1][k];
            float4 bv4 = *(const float4*)&Bs[k][ni * 4];
            acc[0][0] += a0 * bv4.x; acc[0][1] += a0 * bv4.y;
            acc[0][2] += a0 * bv4.z; acc[0][3] += a0 * bv4.w;
            acc[1][0] += a1 * bv4.x; acc[1][1] += a1 * bv4.y;
            acc[1][2] += a1 * bv4.z; acc[1][3] += a1 * bv4.w;
        }
        __syncthreads();
    }
    #pragma unroll
    for (int ii = 0; ii < 2; ii++) {
        int m = m0 + mi * 2 + ii;
        #pragma unroll
        for (int u = 0; u < 4; u++) {
            int n = n0 + ni * 4 + u;
            gHid[(size_t)m * (2 * SD) + n] = fmaxf(acc[ii][u] + b1[n], 0.f);
        }
    }
}

// ---------------------------------------------------------------------------
// Kernel 6: out += gHid @ W2, K-split 2 (atomic into primed out).
// Grid (16, 4, 2), tile 16m x 64n x K256.
// ---------------------------------------------------------------------------
__global__ void __launch_bounds__(256) mlp2_kernel(
    const float* __restrict__ W2, float* __restrict__ out)
{
    __shared__ float As[16][KT + 1];
    __shared__ float Bs[KT][68];
    int m0 = blockIdx.x * 16, n0 = blockIdx.y * 64;
    int kbase = blockIdx.z * 256;
    int t = threadIdx.x;
    int ni = t & 15, mi = t >> 4;
    float acc[4] = {0, 0, 0, 0};

    for (int k0 = kbase; k0 < kbase + 256; k0 += KT) {
        if (t < 128) {
            int lm = t >> 3, lk = t & 7;
            float4 v = *(const float4*)(gHid + (size_t)(m0 + lm) * (2 * SD) + k0 + lk * 4);
            As[lm][lk * 4 + 0] = v.x; As[lm][lk * 4 + 1] = v.y;
            As[lm][lk * 4 + 2] = v.z; As[lm][lk * 4 + 3] = v.w;
        }
        #pragma unroll
        for (int rep = 0; rep < 2; rep++) {
            int i = t + rep * 256;
            int k = i >> 4, nc = i & 15;
            float4 v = *(const float4*)(W2 + (size_t)(k0 + k) * SD + n0 + nc * 4);
            *(float4*)&Bs[k][nc * 4] = v;
        }
        __syncthreads();
        #pragma unroll 8
        for (int k = 0; k < KT; k++) {
            float a = As[mi][k];
            float4 bv4 = *(const float4*)&Bs[k][ni * 4];
            acc[0] += a * bv4.x; acc[1] += a * bv4.y;
            acc[2] += a * bv4.z; acc[3] += a * bv4.w;
        }
        __syncthreads();
    }
    int m = m0 + mi;
    #pragma unroll
    for (int u = 0; u < 4; u++) {
        int n = n0 + ni * 4 + u;
        atomicAdd(&out[(size_t)m * SD + n], acc[u]);
    }
}

// ---------------------------------------------------------------------------
extern "C" void kernel_launch(void* const* d_in, const int* in_sizes, int n_in,
                              void* d_out, int out_size)
{
    const float* features = (const float*)d_in[0];
    const float* slots    = (const float*)d_in[1];
    const float* Wq   = (const float*)d_in[2];
    const float* bq   = (const float*)d_in[3];
    const float* Wk   = (const float*)d_in[4];
    const float* bk   = (const float*)d_in[5];
    const float* Wv   = (const float*)d_in[6];
    const float* bv   = (const float*)d_in[7];
    const float* W_ih = (const float*)d_in[8];
    const float* b_ih = (const float*)d_in[9];
    const float* W_hh = (const float*)d_in[10];
    const float* b_hh = (const float*)d_in[11];
    const float* g_pre  = (const float*)d_in[12];
    const float* b_pre  = (const float*)d_in[13];
    const float* g_post = (const float*)d_in[14];
    const float* b_post = (const float*)d_in[15];
    const float* W1 = (const float*)d_in[16];
    const float* b1 = (const float*)d_in[17];
    const float* W2 = (const float*)d_in[18];
    const float* b2 = (const float*)d_in[19];
    float* out = (float*)d_out;

    prep_kernel<<<BB * 2, 256>>>(slots, Wq, bq, Wk, bk, g_pre, b_pre);

    size_t smem = (size_t)(CC * FST + CC * NJ + NJ * AST) * sizeof(float);
    cudaFuncSetAttribute(main_kernel, cudaFuncAttributeMaxDynamicSharedMemorySize, (int)smem);
    main_kernel<<<dim3(NPIX / TILE_N, BB), 256, smem>>>(features, Wv, bv);

    gru_kernel<<<dim3(NROWS / 64, SD / 32, 8), 256>>>(slots, W_ih, W_hh);
    fin_kernel<<<NROWS / 8, 256>>>(slots, b_ih, b_hh, g_post, b_post, b2, out);
    mlp1_kernel<<<dim3(NROWS / 32, (2 * SD) / 64), 256>>>(W1, b1);
    mlp2_kernel<<<dim3(NROWS / 16, SD / 64, 2), 256>>>(W2, out);
}

// round 8
// speedup vs baseline: 1.1385x; 1.0860x over previous
#include <cuda_runtime.h>
#include <math.h>

// Problem constants
#define BB 32        // batch
#define CC 128       // FEAT_DIM
#define NPIX 4096    // H*W
#define SD 256       // SLOT_DIM
#define NS 8         // N_SLOTS
#define NH 4         // N_HEADS
#define HD 64        // HEAD_DIM
#define NJ 32        // NH*NS  (j = h*8 + s)
#define TILE_N 128
#define NROWS 256    // BB*NS flattened rows
#define FST 128      // featT smem row stride (XOR-swizzled chunks)
#define AST 132      // attn smem row stride (padded)
#define KT 32
#define RS (NROWS * SD)

// Scratch (device globals; no allocation allowed)
__device__ float gA[BB * CC * NJ];      // per-batch folded K-projection (128x32)
__device__ float gSbias[BB * NJ];       // score bias from bk
__device__ float gM[BB * NJ * CC];      // M[b][j][c]
__device__ float gSsum[BB * NJ];        // sum_n attn[b][j]
__device__ float gAgg[RS];              // agg (GRU input x), [row][dim]
__device__ float gLN[RS];               // post-LN of updated
__device__ float gHid[NROWS * 2 * SD];  // MLP hidden (post-ReLU)
__device__ float gPart[6 * RS];         // gRZ[256][512] | gIN[256][256] | gHN[256][256]

#define gRZ (gPart)
#define gIN (gPart + NROWS * 512)
#define gHN (gPart + NROWS * 512 + NROWS * 256)

// ---------------------------------------------------------------------------
// Kernel 1: LN(slots) -> q(half) -> A fold for a head-pair. grid = BB*2 = 64.
// Also zeros gM, gSsum, and ALL of gPart.
// ---------------------------------------------------------------------------
__global__ void __launch_bounds__(256) prep_kernel(
    const float* __restrict__ slots,
    const float* __restrict__ Wq, const float* __restrict__ bq,
    const float* __restrict__ Wk, const float* __restrict__ bk,
    const float* __restrict__ g_pre, const float* __restrict__ b_pre)
{
    __shared__ float ln_s[NS][SD];
    __shared__ float qp[NS][128];
    __shared__ float q_s[NS][128];
    int b = blockIdx.x >> 1, hp = blockIdx.x & 1;
    int t = threadIdx.x;
    int w = t >> 5, lane = t & 31;

    for (int i = t; i < 16 * CC; i += 256)
        gM[b * NJ * CC + hp * 16 * CC + i] = 0.f;
    if (t < 16) gSsum[b * NJ + hp * 16 + t] = 0.f;
    // zero full gPart: 6*RS floats / 64 blocks = 6144 each
    {
        float4* z = (float4*)(gPart + (size_t)blockIdx.x * 6144);
        for (int i = t; i < 1536; i += 256) z[i] = make_float4(0.f, 0.f, 0.f, 0.f);
    }

    {
        const float* row = slots + (size_t)(b * NS + w) * SD;
        float s1 = 0.f, s2 = 0.f;
        for (int k = lane; k < SD; k += 32) { float v = row[k]; s1 += v; s2 += v * v; }
        #pragma unroll
        for (int o = 16; o; o >>= 1) {
            s1 += __shfl_xor_sync(0xffffffffu, s1, o);
            s2 += __shfl_xor_sync(0xffffffffu, s2, o);
        }
        float mu = s1 * (1.f / SD);
        float var = s2 * (1.f / SD) - mu * mu;
        float rs = rsqrtf(var + 1e-5f);
        for (int k = lane; k < SD; k += 32)
            ln_s[w][k] = (row[k] - mu) * rs * g_pre[k] + b_pre[k];
    }
    __syncthreads();

    {
        int dimL = t & 127, ks = t >> 7;
        int dim = hp * 128 + dimL;
        float acc[NS];
        #pragma unroll
        for (int s = 0; s < NS; s++) acc[s] = 0.f;
        int kb = ks * 128;
        #pragma unroll 8
        for (int k = kb; k < kb + 128; k++) {
            float wv = Wq[k * SD + dim];
            #pragma unroll
            for (int s = 0; s < NS; s++) acc[s] += ln_s[s][k] * wv;
        }
        if (ks == 1) {
            #pragma unroll
            for (int s = 0; s < NS; s++) qp[s][dimL] = acc[s];
        }
        __syncthreads();
        if (ks == 0) {
            float bqv = bq[dim];
            #pragma unroll
            for (int s = 0; s < NS; s++) q_s[s][dimL] = acc[s] + qp[s][dimL] + bqv;
        }
    }
    __syncthreads();

    const float scale = 0.125f;
    for (int idx = t; idx < CC * 16; idx += 256) {
        int c = idx >> 4, jl = idx & 15;
        int hl = jl >> 3, s = jl & 7;
        const float* wk = Wk + (size_t)c * SD + (2 * hp + hl) * HD;
        const float* qq = &q_s[s][hl * HD];
        float acc = 0.f;
        #pragma unroll 8
        for (int d = 0; d < HD; d++) acc += wk[d] * qq[d];
        gA[b * CC * NJ + c * NJ + hp * 16 + jl] = acc * scale;
    }
    if (t < 16) {
        int jl = t, hl = jl >> 3, s = jl & 7;
        float acc = 0.f;
        for (int d = 0; d < HD; d++)
            acc += bk[(2 * hp + hl) * HD + d] * q_s[s][hl * HD + d];
        gSbias[b * NJ + hp * 16 + jl] = acc * scale;
    }
}

// ---------------------------------------------------------------------------
// Kernel 2 (heavy): scores + fused softmax + M partials. grid (32, 32).
// ---------------------------------------------------------------------------
__global__ void __launch_bounds__(256) main_kernel(const float* __restrict__ features)
{
    extern __shared__ float sm[];
    float* featT = sm;                     // [CC][FST] swizzled
    float* A_s   = featT + CC * FST;       // [CC][NJ]
    float* attn  = A_s + CC * NJ;          // [NJ][AST]

    int tile = blockIdx.x, b = blockIdx.y;
    int t = threadIdx.x;
    int n0 = tile * TILE_N;

    const float* fb = features + (size_t)b * CC * NPIX + n0;
    for (int i = t; i < CC * TILE_N / 4; i += 256) {
        int c = i >> 5, n4 = i & 31;
        int sw = (n4 ^ (c & 31)) << 2;
        *(float4*)&featT[c * FST + sw] = ((const float4*)(fb + (size_t)c * NPIX))[n4];
    }
    for (int i = t; i < CC * NJ / 4; i += 256)
        ((float4*)A_s)[i] = ((const float4*)(gA + b * CC * NJ))[i];
    __syncthreads();

    // Phase 1: scores + bias + fused softmax
    {
        int jg = t & 7, ng = t >> 3;
        int jb = jg * 4;
        float sbv[4];
        #pragma unroll
        for (int u = 0; u < 4; u++) sbv[u] = gSbias[b * NJ + jb + u];

        float acc[4][4];
        #pragma unroll
        for (int i = 0; i < 4; i++)
            #pragma unroll
            for (int u = 0; u < 4; u++) acc[i][u] = 0.f;
        #pragma unroll 4
        for (int c = 0; c < CC; c++) {
            float4 f = *(const float4*)&featT[c * FST + ((ng ^ (c & 31)) << 2)];
            float4 a = *(const float4*)&A_s[c * NJ + jb];
            float fa[4] = {f.x, f.y, f.z, f.w};
            float aa[4] = {a.x, a.y, a.z, a.w};
            #pragma unroll
            for (int i = 0; i < 4; i++)
                #pragma unroll
                for (int u = 0; u < 4; u++) acc[i][u] += fa[i] * aa[u];
        }
        #pragma unroll
        for (int i = 0; i < 4; i++)
            #pragma unroll
            for (int u = 0; u < 4; u++) acc[i][u] += sbv[u];

        #pragma unroll
        for (int i = 0; i < 4; i++) {
            float m = fmaxf(fmaxf(acc[i][0], acc[i][1]), fmaxf(acc[i][2], acc[i][3]));
            m = fmaxf(m, __shfl_xor_sync(0xffffffffu, m, 1));
            float s = 0.f;
            #pragma unroll
            for (int u = 0; u < 4; u++) { acc[i][u] = __expf(acc[i][u] - m); s += acc[i][u]; }
            s += __shfl_xor_sync(0xffffffffu, s, 1);
            float inv = 1.f / s;
            #pragma unroll
            for (int u = 0; u < 4; u++) acc[i][u] *= inv;
        }

        int nb = ng * 4;
        #pragma unroll
        for (int u = 0; u < 4; u++) {
            float4 v = make_float4(acc[0][u], acc[1][u], acc[2][u], acc[3][u]);
            *(float4*)&attn[(jb + u) * AST + nb] = v;
        }

        float p[4];
        #pragma unroll
        for (int u = 0; u < 4; u++)
            p[u] = acc[0][u] + acc[1][u] + acc[2][u] + acc[3][u];
        #pragma unroll
        for (int u = 0; u < 4; u++) {
            p[u] += __shfl_xor_sync(0xffffffffu, p[u], 8);
            p[u] += __shfl_xor_sync(0xffffffffu, p[u], 16);
        }
        if ((t & 31) < 8) {
            #pragma unroll
            for (int u = 0; u < 4; u++) atomicAdd(&gSsum[b * NJ + jb + u], p[u]);
        }
    }
    __syncthreads();

    // Phase 3: warp owns 4 j rows, lane owns c = {cg, cg+32, cg+64, cg+96}
    {
        int jb = (t >> 5) * 4, cg = t & 31;
        float acc[4][4];
        #pragma unroll
        for (int u = 0; u < 4; u++)
            #pragma unroll
            for (int r = 0; r < 4; r++) acc[u][r] = 0.f;
        for (int nn = 0; nn < TILE_N; nn += 4) {
            float4 av[4];
            #pragma unroll
            for (int u = 0; u < 4; u++)
                av[u] = *(const float4*)&attn[(jb + u) * AST + nn];
            int swc = ((nn >> 2) ^ cg) << 2;
            #pragma unroll
            for (int r = 0; r < 4; r++) {
                float4 fv = *(const float4*)&featT[(cg + 32 * r) * FST + swc];
                #pragma unroll
                for (int u = 0; u < 4; u++)
                    acc[u][r] += av[u].x * fv.x + av[u].y * fv.y
                               + av[u].z * fv.z + av[u].w * fv.w;
            }
        }
        float* gm = gM + b * NJ * CC;
        #pragma unroll
        for (int u = 0; u < 4; u++)
            #pragma unroll
            for (int r = 0; r < 4; r++)
                atomicAdd(&gm[(jb + u) * CC + cg + 32 * r], acc[u][r]);
    }
}

// ---------------------------------------------------------------------------
// Kernel 3: agg[row][dim] = M[b][j] @ Wv[:,dim] + Ssum*bv. Block per (b, head).
// ---------------------------------------------------------------------------
__global__ void __launch_bounds__(256) agg_kernel(
    const float* __restrict__ Wv, const float* __restrict__ bv)
{
    __shared__ float Ms[NS][CC];
    __shared__ float Wvs[CC][HD];
    int b = blockIdx.x >> 2, h = blockIdx.x & 3;
    int t = threadIdx.x;
    {
        int s = t >> 5, c4 = t & 31;
        ((float4*)&Ms[s][0])[c4] =
            ((const float4*)(gM + (size_t)b * NJ * CC + (h * 8 + s) * CC))[c4];
    }
    #pragma unroll
    for (int j = 0; j < 8; j++) {
        int i = t + j * 256;
        int c = i >> 4, d4 = i & 15;
        ((float4*)&Wvs[c][0])[d4] =
            ((const float4*)(Wv + (size_t)c * SD + h * HD))[d4];
    }
    __syncthreads();
    #pragma unroll
    for (int rep = 0; rep < 2; rep++) {
        int o = t + rep * 256;
        int s = o >> 6, d = o & 63;
        int j = h * 8 + s;
        float acc = gSsum[b * NJ + j] * bv[h * HD + d];
        #pragma unroll 8
        for (int c = 0; c < CC; c++) acc += Ms[s][c] * Wvs[c][d];
        gAgg[(size_t)(b * NS + s) * SD + h * HD + d] = acc;
    }
}

// ---------------------------------------------------------------------------
// Kernel 4: GRU gate GEMM. Tile 64m x 32d x 3 gates, K-split 2, phase-split 2.
// grid (4, 8, 4) = 128 blocks. Atomic into zero-primed gPart.
// ---------------------------------------------------------------------------
__global__ void __launch_bounds__(256) gru_kernel(
    const float* __restrict__ slots,
    const float* __restrict__ W_ih, const float* __restrict__ W_hh)
{
    __shared__ float As[64][KT + 1];
    __shared__ float Bs[3][32][KT + 1];
    int m0 = blockIdx.x * 64, dim0 = blockIdx.y * 32;
    int phase = blockIdx.z >> 1, kh = blockIdx.z & 1;
    int t = threadIdx.x;
    int di = t & 15, mi = t >> 4;

    float accg[3][4][2];
    #pragma unroll
    for (int g = 0; g < 3; g++)
        #pragma unroll
        for (int i = 0; i < 4; i++)
            #pragma unroll
            for (int j = 0; j < 2; j++) accg[g][i][j] = 0.f;

    int lk = t & 7;
    const float* Ag = phase ? slots : gAgg;
    const float* Wg = phase ? W_hh : W_ih;
    int kbase = kh * 128;

    for (int k0 = kbase; k0 < kbase + 128; k0 += KT) {
        #pragma unroll
        for (int rep = 0; rep < 2; rep++) {
            int idx = t + rep * 256;
            int row = idx >> 3;
            float4 v = *(const float4*)(Ag + (size_t)(m0 + row) * SD + k0 + lk * 4);
            As[row][lk * 4 + 0] = v.x; As[row][lk * 4 + 1] = v.y;
            As[row][lk * 4 + 2] = v.z; As[row][lk * 4 + 3] = v.w;
        }
        {
            int lm = t >> 3;
            #pragma unroll
            for (int g = 0; g < 3; g++) {
                float4 v = *(const float4*)(Wg + (size_t)(g * SD + dim0 + lm) * SD + k0 + lk * 4);
                Bs[g][lm][lk * 4 + 0] = v.x; Bs[g][lm][lk * 4 + 1] = v.y;
                Bs[g][lm][lk * 4 + 2] = v.z; Bs[g][lm][lk * 4 + 3] = v.w;
            }
        }
        __syncthreads();
        #pragma unroll 4
        for (int k = 0; k < KT; k++) {
            float a[4];
            #pragma unroll
            for (int i = 0; i < 4; i++) a[i] = As[mi * 4 + i][k];
            #pragma unroll
            for (int g = 0; g < 3; g++) {
                float b0 = Bs[g][di * 2 + 0][k];
                float b1 = Bs[g][di * 2 + 1][k];
                #pragma unroll
                for (int i = 0; i < 4; i++) {
                    accg[g][i][0] += a[i] * b0;
                    accg[g][i][1] += a[i] * b1;
                }
            }
        }
        __syncthreads();
    }

    float* dstN = phase ? gHN : gIN;
    #pragma unroll
    for (int i = 0; i < 4; i++) {
        int m = m0 + mi * 4 + i;
        #pragma unroll
        for (int j = 0; j < 2; j++) {
            int d = dim0 + di * 2 + j;
            atomicAdd(&gRZ[(size_t)m * 512 + d], accg[0][i][j]);
            atomicAdd(&gRZ[(size_t)m * 512 + 256 + d], accg[1][i][j]);
            atomicAdd(&dstN[(size_t)m * SD + d], accg[2][i][j]);
        }
    }
}

// ---------------------------------------------------------------------------
// Kernel 5: GRU nonlin + post-LN + prime out = upd + b2.
// One ROW per block (grid=256), one DIM per thread: single parallel load
// round, block-wide LN reduction.
// ---------------------------------------------------------------------------
__global__ void __launch_bounds__(256) fin_kernel(
    const float* __restrict__ slots,
    const float* __restrict__ b_ih, const float* __restrict__ b_hh,
    const float* __restrict__ g_post, const float* __restrict__ b_post,
    const float* __restrict__ b2, float* __restrict__ out)
{
    __shared__ float red[16];
    __shared__ float stat[2];
    int row = blockIdx.x;
    int d = threadIdx.x;
    size_t ro = (size_t)row * SD;

    float rz_r = gRZ[(size_t)row * 512 + d] + b_ih[d] + b_hh[d];
    float rz_z = gRZ[(size_t)row * 512 + 256 + d] + b_ih[SD + d] + b_hh[SD + d];
    float in_ = gIN[ro + d] + b_ih[2 * SD + d];
    float hn  = gHN[ro + d] + b_hh[2 * SD + d];
    float r = 1.f / (1.f + expf(-rz_r));
    float z = 1.f / (1.f + expf(-rz_z));
    float nn = tanhf(in_ + r * hn);
    float hp = slots[ro + d];
    float v = (1.f - z) * nn + z * hp;
    out[ro + d] = v + b2[d];

    // block-wide LN reduction over 256 threads
    float s1 = v, s2 = v * v;
    #pragma unroll
    for (int o = 16; o; o >>= 1) {
        s1 += __shfl_xor_sync(0xffffffffu, s1, o);
        s2 += __shfl_xor_sync(0xffffffffu, s2, o);
    }
    int w = d >> 5, lane = d & 31;
    if (lane == 0) { red[w] = s1; red[8 + w] = s2; }
    __syncthreads();
    if (d == 0) {
        float t1 = 0.f, t2 = 0.f;
        #pragma unroll
        for (int i = 0; i < 8; i++) { t1 += red[i]; t2 += red[8 + i]; }
        float mu = t1 * (1.f / SD);
        float var = t2 * (1.f / SD) - mu * mu;
        stat[0] = mu;
        stat[1] = rsqrtf(var + 1e-5f);
    }
    __syncthreads();
    gLN[ro + d] = (v - stat[0]) * stat[1] * g_post[d] + b_post[d];
}

// ---------------------------------------------------------------------------
// Kernel 6: gHid = relu(gLN @ W1 + b1). Grid (16, 8) = 128, tile 16x64.
// ---------------------------------------------------------------------------
__global__ void __launch_bounds__(256) mlp1_kernel(
    const float* __restrict__ W1, const float* __restrict__ b1)
{
    __shared__ float As[16][KT + 1];
    __shared__ float Bs[KT][68];
    int m0 = blockIdx.x * 16, n0 = blockIdx.y * 64;
    int t = threadIdx.x;
    int ni = t & 15, mi = t >> 4;
    float acc[4] = {0, 0, 0, 0};

    for (int k0 = 0; k0 < SD; k0 += KT) {
        if (t < 128) {
            int lm = t >> 3, lk = t & 7;
            float4 v = *(const float4*)(gLN + (size_t)(m0 + lm) * SD + k0 + lk * 4);
            As[lm][lk * 4 + 0] = v.x; As[lm][lk * 4 + 1] = v.y;
            As[lm][lk * 4 + 2] = v.z; As[lm][lk * 4 + 3] = v.w;
        }
        #pragma unroll
        for (int rep = 0; rep < 2; rep++) {
            int i = t + rep * 256;
            int k = i >> 4, nc = i & 15;
            float4 v = *(const float4*)(W1 + (size_t)(k0 + k) * (2 * SD) + n0 + nc * 4);
            *(float4*)&Bs[k][nc * 4] = v;
        }
        __syncthreads();
        #pragma unroll 8
        for (int k = 0; k < KT; k++) {
            float a = As[mi][k];
            float4 bv4 = *(const float4*)&Bs[k][ni * 4];
            acc[0] += a * bv4.x; acc[1] += a * bv4.y;
            acc[2] += a * bv4.z; acc[3] += a * bv4.w;
        }
        __syncthreads();
    }
    int m = m0 + mi;
    #pragma unroll
    for (int u = 0; u < 4; u++) {
        int n = n0 + ni * 4 + u;
        gHid[(size_t)m * (2 * SD) + n] = fmaxf(acc[u] + b1[n], 0.f);
    }
}

// ---------------------------------------------------------------------------
// Kernel 7: out += gHid @ W2, K-split 2 (atomic into primed out).
// Grid (16, 4, 2), tile 16m x 64n x K256.
// ---------------------------------------------------------------------------
__global__ void __launch_bounds__(256) mlp2_kernel(
    const float* __restrict__ W2, float* __restrict__ out)
{
    __shared__ float As[16][KT + 1];
    __shared__ float Bs[KT][68];
    int m0 = blockIdx.x * 16, n0 = blockIdx.y * 64;
    int kbase = blockIdx.z * 256;
    int t = threadIdx.x;
    int ni = t & 15, mi = t >> 4;
    float acc[4] = {0, 0, 0, 0};

    for (int k0 = kbase; k0 < kbase + 256; k0 += KT) {
        if (t < 128) {
            int lm = t >> 3, lk = t & 7;
            float4 v = *(const float4*)(gHid + (size_t)(m0 + lm) * (2 * SD) + k0 + lk * 4);
            As[lm][lk * 4 + 0] = v.x; As[lm][lk * 4 + 1] = v.y;
            As[lm][lk * 4 + 2] = v.z; As[lm][lk * 4 + 3] = v.w;
        }
        #pragma unroll
        for (int rep = 0; rep < 2; rep++) {
            int i = t + rep * 256;
            int k = i >> 4, nc = i & 15;
            float4 v = *(const float4*)(W2 + (size_t)(k0 + k) * SD + n0 + nc * 4);
            *(float4*)&Bs[k][nc * 4] = v;
        }
        __syncthreads();
        #pragma unroll 8
        for (int k = 0; k < KT; k++) {
            float a = As[mi][k];
            float4 bv4 = *(const float4*)&Bs[k][ni * 4];
            acc[0] += a * bv4.x; acc[1] += a * bv4.y;
            acc[2] += a * bv4.z; acc[3] += a * bv4.w;
        }
        __syncthreads();
    }
    int m = m0 + mi;
    #pragma unroll
    for (int u = 0; u < 4; u++) {
        int n = n0 + ni * 4 + u;
        atomicAdd(&out[(size_t)m * SD + n], acc[u]);
    }
}

// ---------------------------------------------------------------------------
extern "C" void kernel_launch(void* const* d_in, const int* in_sizes, int n_in,
                              void* d_out, int out_size)
{
    const float* features = (const float*)d_in[0];
    const float* slots    = (const float*)d_in[1];
    const float* Wq   = (const float*)d_in[2];
    const float* bq   = (const float*)d_in[3];
    const float* Wk   = (const float*)d_in[4];
    const float* bk   = (const float*)d_in[5];
    const float* Wv   = (const float*)d_in[6];
    const float* bv   = (const float*)d_in[7];
    const float* W_ih = (const float*)d_in[8];
    const float* b_ih = (const float*)d_in[9];
    const float* W_hh = (const float*)d_in[10];
    const float* b_hh = (const float*)d_in[11];
    const float* g_pre  = (const float*)d_in[12];
    const float* b_pre  = (const float*)d_in[13];
    const float* g_post = (const float*)d_in[14];
    const float* b_post = (const float*)d_in[15];
    const float* W1 = (const float*)d_in[16];
    const float* b1 = (const float*)d_in[17];
    const float* W2 = (const float*)d_in[18];
    const float* b2 = (const float*)d_in[19];
    float* out = (float*)d_out;

    prep_kernel<<<BB * 2, 256>>>(slots, Wq, bq, Wk, bk, g_pre, b_pre);

    size_t smem = (size_t)(CC * FST + CC * NJ + NJ * AST) * sizeof(float);
    cudaFuncSetAttribute(main_kernel, cudaFuncAttributeMaxDynamicSharedMemorySize, (int)smem);
    main_kernel<<<dim3(NPIX / TILE_N, BB), 256, smem>>>(features);

    agg_kernel<<<BB * NH, 256>>>(Wv, bv);
    gru_kernel<<<dim3(NROWS / 64, SD / 32, 4), 256>>>(slots, W_ih, W_hh);
    fin_kernel<<<NROWS, 256>>>(slots, b_ih, b_hh, g_post, b_post, b2, out);
    mlp1_kernel<<<dim3(NROWS / 16, (2 * SD) / 64), 256>>>(W1, b1);
    mlp2_kernel<<<dim3(NROWS / 16, SD / 64, 2), 256>>>(W2, out);
}

// round 13
// speedup vs baseline: 1.1677x; 1.0257x over previous
#include <cuda_runtime.h>
#include <math.h>
#include <stdint.h>

// Problem constants
#define BB 32        // batch
#define CC 128       // FEAT_DIM
#define NPIX 4096    // H*W
#define SD 256       // SLOT_DIM
#define NS 8         // N_SLOTS
#define NH 4         // N_HEADS
#define HD 64        // HEAD_DIM
#define NJ 32        // NH*NS  (j = h*8 + s)
#define TILE_N 128
#define NROWS 256    // BB*NS flattened rows
#define FST 128      // featT smem row stride (XOR-swizzled chunks)
#define AST 132      // attn smem row stride (padded)
#define KT 32
#define RS (NROWS * SD)

// Scratch (device globals; no allocation allowed)
__device__ float gA[BB * CC * NJ];      // per-batch folded K-projection (128x32)
__device__ float gSbias[BB * NJ];       // score bias from bk
__device__ float gM[BB * NJ * CC];      // M[b][j][c]
__device__ float gSsum[BB * NJ];        // sum_n attn[b][j]
__device__ float gAgg[RS];              // agg (GRU input x), [row][dim]
__device__ float gLN[RS];               // post-LN of updated
__device__ float gHid[NROWS * 2 * SD];  // MLP hidden (post-ReLU)
__device__ float gPart[6 * RS];         // gRZ[256][512] | gIN[256][256] | gHN[256][256]

#define gRZ (gPart)
#define gIN (gPart + NROWS * 512)
#define gHN (gPart + NROWS * 512 + NROWS * 256)

// scalar read index into XOR-swizzled featT
__device__ __forceinline__ int fidx(int c, int n) {
    return c * FST + ((((n >> 2) ^ (c & 31))) << 2) + (n & 3);
}
__device__ __forceinline__ uint32_t to_tf32(float f) {
    uint32_t r;
    asm("cvt.rna.tf32.f32 %0, %1;" : "=r"(r) : "f"(f));
    return r;
}

// ---------------------------------------------------------------------------
// Kernel 1: LN(slots) -> q(half) -> A fold for a head-pair. grid = BB*2 = 64.
// Also zeros gM, gSsum, and ALL of gPart.
// ---------------------------------------------------------------------------
__global__ void __launch_bounds__(256) prep_kernel(
    const float* __restrict__ slots,
    const float* __restrict__ Wq, const float* __restrict__ bq,
    const float* __restrict__ Wk, const float* __restrict__ bk,
    const float* __restrict__ g_pre, const float* __restrict__ b_pre)
{
    __shared__ float ln_s[NS][SD];
    __shared__ float qp[NS][128];
    __shared__ float q_s[NS][128];
    int b = blockIdx.x >> 1, hp = blockIdx.x & 1;
    int t = threadIdx.x;
    int w = t >> 5, lane = t & 31;

    for (int i = t; i < 16 * CC; i += 256)
        gM[b * NJ * CC + hp * 16 * CC + i] = 0.f;
    if (t < 16) gSsum[b * NJ + hp * 16 + t] = 0.f;
    {
        float4* z = (float4*)(gPart + (size_t)blockIdx.x * 6144);
        for (int i = t; i < 1536; i += 256) z[i] = make_float4(0.f, 0.f, 0.f, 0.f);
    }

    {
        const float* row = slots + (size_t)(b * NS + w) * SD;
        float s1 = 0.f, s2 = 0.f;
        for (int k = lane; k < SD; k += 32) { float v = row[k]; s1 += v; s2 += v * v; }
        #pragma unroll
        for (int o = 16; o; o >>= 1) {
            s1 += __shfl_xor_sync(0xffffffffu, s1, o);
            s2 += __shfl_xor_sync(0xffffffffu, s2, o);
        }
        float mu = s1 * (1.f / SD);
        float var = s2 * (1.f / SD) - mu * mu;
        float rs = rsqrtf(var + 1e-5f);
        for (int k = lane; k < SD; k += 32)
            ln_s[w][k] = (row[k] - mu) * rs * g_pre[k] + b_pre[k];
    }
    __syncthreads();

    {
        int dimL = t & 127, ks = t >> 7;
        int dim = hp * 128 + dimL;
        float acc[NS];
        #pragma unroll
        for (int s = 0; s < NS; s++) acc[s] = 0.f;
        int kb = ks * 128;
        #pragma unroll 8
        for (int k = kb; k < kb + 128; k++) {
            float wv = Wq[k * SD + dim];
            #pragma unroll
            for (int s = 0; s < NS; s++) acc[s] += ln_s[s][k] * wv;
        }
        if (ks == 1) {
            #pragma unroll
            for (int s = 0; s < NS; s++) qp[s][dimL] = acc[s];
        }
        __syncthreads();
        if (ks == 0) {
            float bqv = bq[dim];
            #pragma unroll
            for (int s = 0; s < NS; s++) q_s[s][dimL] = acc[s] + qp[s][dimL] + bqv;
        }
    }
    __syncthreads();

    const float scale = 0.125f;
    for (int idx = t; idx < CC * 16; idx += 256) {
        int c = idx >> 4, jl = idx & 15;
        int hl = jl >> 3, s = jl & 7;
        const float* wk = Wk + (size_t)c * SD + (2 * hp + hl) * HD;
        const float* qq = &q_s[s][hl * HD];
        float acc = 0.f;
        #pragma unroll 8
        for (int d = 0; d < HD; d++) acc += wk[d] * qq[d];
        gA[b * CC * NJ + c * NJ + hp * 16 + jl] = acc * scale;
    }
    if (t < 16) {
        int jl = t, hl = jl >> 3, s = jl & 7;
        float acc = 0.f;
        for (int d = 0; d < HD; d++)
            acc += bk[(2 * hp + hl) * HD + d] * q_s[s][hl * HD + d];
        gSbias[b * NJ + hp * 16 + jl] = acc * scale;
    }
}

// ---------------------------------------------------------------------------
// Kernel 2 (heavy): scores (SIMT fp32) + fused softmax + M partials via
// warp-level TF32 mma.sync (tensor pipe). grid (32, 32).
// ---------------------------------------------------------------------------
__global__ void __launch_bounds__(256) main_kernel(const float* __restrict__ features)
{
    extern __shared__ float sm[];
    float* featT = sm;                     // [CC][FST] swizzled
    float* A_s   = featT + CC * FST;       // [CC][NJ]
    float* attn  = A_s + CC * NJ;          // [NJ][AST]

    int tile = blockIdx.x, b = blockIdx.y;
    int t = threadIdx.x;
    int wid = t >> 5, lane = t & 31;
    int n0 = tile * TILE_N;

    const float* fb = features + (size_t)b * CC * NPIX + n0;
    for (int i = t; i < CC * TILE_N / 4; i += 256) {
        int c = i >> 5, n4 = i & 31;
        int sw = (n4 ^ (c & 31)) << 2;
        *(float4*)&featT[c * FST + sw] = ((const float4*)(fb + (size_t)c * NPIX))[n4];
    }
    for (int i = t; i < CC * NJ / 4; i += 256)
        ((float4*)A_s)[i] = ((const float4*)(gA + b * CC * NJ))[i];
    __syncthreads();

    // Phase 1: scores + bias + fused softmax (fp32 SIMT)
    {
        int jg = t & 7, ng = t >> 3;
        int jb = jg * 4;
        float sbv[4];
        #pragma unroll
        for (int u = 0; u < 4; u++) sbv[u] = gSbias[b * NJ + jb + u];

        float acc[4][4];
        #pragma unroll
        for (int i = 0; i < 4; i++)
            #pragma unroll
            for (int u = 0; u < 4; u++) acc[i][u] = 0.f;
        #pragma unroll 4
        for (int c = 0; c < CC; c++) {
            float4 f = *(const float4*)&featT[c * FST + ((ng ^ (c & 31)) << 2)];
            float4 a = *(const float4*)&A_s[c * NJ + jb];
            float fa[4] = {f.x, f.y, f.z, f.w};
            float aa[4] = {a.x, a.y, a.z, a.w};
            #pragma unroll
            for (int i = 0; i < 4; i++)
                #pragma unroll
                for (int u = 0; u < 4; u++) acc[i][u] += fa[i] * aa[u];
        }
        #pragma unroll
        for (int i = 0; i < 4; i++)
            #pragma unroll
            for (int u = 0; u < 4; u++) acc[i][u] += sbv[u];

        #pragma unroll
        for (int i = 0; i < 4; i++) {
            float m = fmaxf(fmaxf(acc[i][0], acc[i][1]), fmaxf(acc[i][2], acc[i][3]));
            m = fmaxf(m, __shfl_xor_sync(0xffffffffu, m, 1));
            float s = 0.f;
            #pragma unroll
            for (int u = 0; u < 4; u++) { acc[i][u] = __expf(acc[i][u] - m); s += acc[i][u]; }
            s += __shfl_xor_sync(0xffffffffu, s, 1);
            float inv = 1.f / s;
            #pragma unroll
            for (int u = 0; u < 4; u++) acc[i][u] *= inv;
        }

        int nb = ng * 4;
        #pragma unroll
        for (int u = 0; u < 4; u++) {
            float4 v = make_float4(acc[0][u], acc[1][u], acc[2][u], acc[3][u]);
            *(float4*)&attn[(jb + u) * AST + nb] = v;
        }

        float p[4];
        #pragma unroll
        for (int u = 0; u < 4; u++)
            p[u] = acc[0][u] + acc[1][u] + acc[2][u] + acc[3][u];
        #pragma unroll
        for (int u = 0; u < 4; u++) {
            p[u] += __shfl_xor_sync(0xffffffffu, p[u], 8);
            p[u] += __shfl_xor_sync(0xffffffffu, p[u], 16);
        }
        if ((t & 31) < 8) {
            #pragma unroll
            for (int u = 0; u < 4; u++) atomicAdd(&gSsum[b * NJ + jb + u], p[u]);
        }
    }
    __syncthreads();

    // Phase 3 via mma.sync TF32: warp wid owns c rows [wid*16, wid*16+16),
    // computes D[c16][j32] = sum_n featT[c][n] * attn[j][n].
    // A = featT (m=c, k=n, row-major), B = attn (k=n, col=j, col-major).
    {
        int cb = wid * 16;
        int row = lane >> 2, qd = lane & 3;
        float d[4][4];
        #pragma unroll
        for (int jt = 0; jt < 4; jt++)
            #pragma unroll
            for (int u = 0; u < 4; u++) d[jt][u] = 0.f;

        #pragma unroll 4
        for (int nb = 0; nb < TILE_N; nb += 8) {
            int c0 = cb + row, c1 = cb + row + 8;
            int na = nb + qd, nc = nb + qd + 4;
            uint32_t a0 = to_tf32(featT[fidx(c0, na)]);
            uint32_t a1 = to_tf32(featT[fidx(c1, na)]);
            uint32_t a2 = to_tf32(featT[fidx(c0, nc)]);
            uint32_t a3 = to_tf32(featT[fidx(c1, nc)]);
            #pragma unroll
            for (int jt = 0; jt < 4; jt++) {
                int j = jt * 8 + row;
                uint32_t b0 = to_tf32(attn[j * AST + nb + qd]);
                uint32_t b1 = to_tf32(attn[j * AST + nb + qd + 4]);
                asm volatile(
                    "mma.sync.aligned.m16n8k8.row.col.f32.tf32.tf32.f32 "
                    "{%0,%1,%2,%3}, {%4,%5,%6,%7}, {%8,%9}, {%0,%1,%2,%3};"
                    : "+f"(d[jt][0]), "+f"(d[jt][1]), "+f"(d[jt][2]), "+f"(d[jt][3])
                    : "r"(a0), "r"(a1), "r"(a2), "r"(a3), "r"(b0), "r"(b1));
            }
        }

        float* gm = gM + b * NJ * CC;
        #pragma unroll
        for (int jt = 0; jt < 4; jt++) {
            int j0 = jt * 8 + 2 * qd;
            atomicAdd(&gm[j0 * CC + cb + row],           d[jt][0]);
            atomicAdd(&gm[(j0 + 1) * CC + cb + row],     d[jt][1]);
            atomicAdd(&gm[j0 * CC + cb + row + 8],       d[jt][2]);
            atomicAdd(&gm[(j0 + 1) * CC + cb + row + 8], d[jt][3]);
        }
    }
}

// ---------------------------------------------------------------------------
// Kernel 3: agg[row][dim] = M[b][j] @ Wv[:,dim] + Ssum*bv. Block per (b, head).
// ---------------------------------------------------------------------------
__global__ void __launch_bounds__(256) agg_kernel(
    const float* __restrict__ Wv, const float* __restrict__ bv)
{
    __shared__ float Ms[NS][CC];
    __shared__ float Wvs[CC][HD];
    int b = blockIdx.x >> 2, h = blockIdx.x & 3;
    int t = threadIdx.x;
    {
        int s = t >> 5, c4 = t & 31;
        ((float4*)&Ms[s][0])[c4] =
            ((const float4*)(gM + (size_t)b * NJ * CC + (h * 8 + s) * CC))[c4];
    }
    #pragma unroll
    for (int j = 0; j < 8; j++) {
        int i = t + j * 256;
        int c = i >> 4, d4 = i & 15;
        ((float4*)&Wvs[c][0])[d4] =
            ((const float4*)(Wv + (size_t)c * SD + h * HD))[d4];
    }
    __syncthreads();
    #pragma unroll
    for (int rep = 0; rep < 2; rep++) {
        int o = t + rep * 256;
        int s = o >> 6, d = o & 63;
        int j = h * 8 + s;
        float acc = gSsum[b * NJ + j] * bv[h * HD + d];
        #pragma unroll 8
        for (int c = 0; c < CC; c++) acc += Ms[s][c] * Wvs[c][d];
        gAgg[(size_t)(b * NS + s) * SD + h * HD + d] = acc;
    }
}

// ---------------------------------------------------------------------------
// Kernel 4: GRU gate GEMM. Tile 64m x 32d x 3 gates, K-split 2, phase-split 2.
// grid (4, 8, 4) = 128 blocks. Atomic into zero-primed gPart.
// ---------------------------------------------------------------------------
__global__ void __launch_bounds__(256) gru_kernel(
    const float* __restrict__ slots,
    const float* __restrict__ W_ih, const float* __restrict__ W_hh)
{
    __shared__ float As[64][KT + 1];
    __shared__ float Bs[3][32][KT + 1];
    int m0 = blockIdx.x * 64, dim0 = blockIdx.y * 32;
    int phase = blockIdx.z >> 1, kh = blockIdx.z & 1;
    int t = threadIdx.x;
    int di = t & 15, mi = t >> 4;

    float accg[3][4][2];
    #pragma unroll
    for (int g = 0; g < 3; g++)
        #pragma unroll
        for (int i = 0; i < 4; i++)
            #pragma unroll
            for (int j = 0; j < 2; j++) accg[g][i][j] = 0.f;

    int lk = t & 7;
    const float* Ag = phase ? slots : gAgg;
    const float* Wg = phase ? W_hh : W_ih;
    int kbase = kh * 128;

    for (int k0 = kbase; k0 < kbase + 128; k0 += KT) {
        #pragma unroll
        for (int rep = 0; rep < 2; rep++) {
            int idx = t + rep * 256;
            int row = idx >> 3;
            float4 v = *(const float4*)(Ag + (size_t)(m0 + row) * SD + k0 + lk * 4);
            As[row][lk * 4 + 0] = v.x; As[row][lk * 4 + 1] = v.y;
            As[row][lk * 4 + 2] = v.z; As[row][lk * 4 + 3] = v.w;
        }
        {
            int lm = t >> 3;
            #pragma unroll
            for (int g = 0; g < 3; g++) {
                float4 v = *(const float4*)(Wg + (size_t)(g * SD + dim0 + lm) * SD + k0 + lk * 4);
                Bs[g][lm][lk * 4 + 0] = v.x; Bs[g][lm][lk * 4 + 1] = v.y;
                Bs[g][lm][lk * 4 + 2] = v.z; Bs[g][lm][lk * 4 + 3] = v.w;
            }
        }
        __syncthreads();
        #pragma unroll 4
        for (int k = 0; k < KT; k++) {
            float a[4];
            #pragma unroll
            for (int i = 0; i < 4; i++) a[i] = As[mi * 4 + i][k];
            #pragma unroll
            for (int g = 0; g < 3; g++) {
                float b0 = Bs[g][di * 2 + 0][k];
                float b1 = Bs[g][di * 2 + 1][k];
                #pragma unroll
                for (int i = 0; i < 4; i++) {
                    accg[g][i][0] += a[i] * b0;
                    accg[g][i][1] += a[i] * b1;
                }
            }
        }
        __syncthreads();
    }

    float* dstN = phase ? gHN : gIN;
    #pragma unroll
    for (int i = 0; i < 4; i++) {
        int m = m0 + mi * 4 + i;
        #pragma unroll
        for (int j = 0; j < 2; j++) {
            int d = dim0 + di * 2 + j;
            atomicAdd(&gRZ[(size_t)m * 512 + d], accg[0][i][j]);
            atomicAdd(&gRZ[(size_t)m * 512 + 256 + d], accg[1][i][j]);
            atomicAdd(&dstN[(size_t)m * SD + d], accg[2][i][j]);
        }
    }
}

// ---------------------------------------------------------------------------
// Kernel 5: GRU nonlin + post-LN + prime out = upd + b2. One row per block.
// ---------------------------------------------------------------------------
__global__ void __launch_bounds__(256) fin_kernel(
    const float* __restrict__ slots,
    const float* __restrict__ b_ih, const float* __restrict__ b_hh,
    const float* __restrict__ g_post, const float* __restrict__ b_post,
    const float* __restrict__ b2, float* __restrict__ out)
{
    __shared__ float red[16];
    __shared__ float stat[2];
    int row = blockIdx.x;
    int d = threadIdx.x;
    size_t ro = (size_t)row * SD;

    float rz_r = gRZ[(size_t)row * 512 + d] + b_ih[d] + b_hh[d];
    float rz_z = gRZ[(size_t)row * 512 + 256 + d] + b_ih[SD + d] + b_hh[SD + d];
    float in_ = gIN[ro + d] + b_ih[2 * SD + d];
    float hn  = gHN[ro + d] + b_hh[2 * SD + d];
    float r = 1.f / (1.f + expf(-rz_r));
    float z = 1.f / (1.f + expf(-rz_z));
    float nn = tanhf(in_ + r * hn);
    float hp = slots[ro + d];
    float v = (1.f - z) * nn + z * hp;
    out[ro + d] = v + b2[d];

    float s1 = v, s2 = v * v;
    #pragma unroll
    for (int o = 16; o; o >>= 1) {
        s1 += __shfl_xor_sync(0xffffffffu, s1, o);
        s2 += __shfl_xor_sync(0xffffffffu, s2, o);
    }
    int w = d >> 5, lane = d & 31;
    if (lane == 0) { red[w] = s1; red[8 + w] = s2; }
    __syncthreads();
    if (d == 0) {
        float t1 = 0.f, t2 = 0.f;
        #pragma unroll
        for (int i = 0; i < 8; i++) { t1 += red[i]; t2 += red[8 + i]; }
        float mu = t1 * (1.f / SD);
        float var = t2 * (1.f / SD) - mu * mu;
        stat[0] = mu;
        stat[1] = rsqrtf(var + 1e-5f);
    }
    __syncthreads();
    gLN[ro + d] = (v - stat[0]) * stat[1] * g_post[d] + b_post[d];
}

// ---------------------------------------------------------------------------
// Kernel 6: gHid = relu(gLN @ W1 + b1). Grid (16, 8) = 128, tile 16x64.
// ---------------------------------------------------------------------------
__global__ void __launch_bounds__(256) mlp1_kernel(
    const float* __restrict__ W1, const float* __restrict__ b1)
{
    __shared__ float As[16][KT + 1];
    __shared__ float Bs[KT][68];
    int m0 = blockIdx.x * 16, n0 = blockIdx.y * 64;
    int t = threadIdx.x;
    int ni = t & 15, mi = t >> 4;
    float acc[4] = {0, 0, 0, 0};

    for (int k0 = 0; k0 < SD; k0 += KT) {
        if (t < 128) {
            int lm = t >> 3, lk = t & 7;
            float4 v = *(const float4*)(gLN + (size_t)(m0 + lm) * SD + k0 + lk * 4);
            As[lm][lk * 4 + 0] = v.x; As[lm][lk * 4 + 1] = v.y;
            As[lm][lk * 4 + 2] = v.z; As[lm][lk * 4 + 3] = v.w;
        }
        #pragma unroll
        for (int rep = 0; rep < 2; rep++) {
            int i = t + rep * 256;
            int k = i >> 4, nc = i & 15;
            float4 v = *(const float4*)(W1 + (size_t)(k0 + k) * (2 * SD) + n0 + nc * 4);
            *(float4*)&Bs[k][nc * 4] = v;
        }
        __syncthreads();
        #pragma unroll 8
        for (int k = 0; k < KT; k++) {
            float a = As[mi][k];
            float4 bv4 = *(const float4*)&Bs[k][ni * 4];
            acc[0] += a * bv4.x; acc[1] += a * bv4.y;
            acc[2] += a * bv4.z; acc[3] += a * bv4.w;
        }
        __syncthreads();
    }
    int m = m0 + mi;
    #pragma unroll
    for (int u = 0; u < 4; u++) {
        int n = n0 + ni * 4 + u;
        gHid[(size_t)m * (2 * SD) + n] = fmaxf(acc[u] + b1[n], 0.f);
    }
}

// ---------------------------------------------------------------------------
// Kernel 7: out += gHid @ W2, K-split 2 (atomic into primed out).
// Grid (16, 4, 2), tile 16m x 64n x K256.
// ---------------------------------------------------------------------------
__global__ void __launch_bounds__(256) mlp2_kernel(
    const float* __restrict__ W2, float* __restrict__ out)
{
    __shared__ float As[16][KT + 1];
    __shared__ float Bs[KT][68];
    int m0 = blockIdx.x * 16, n0 = blockIdx.y * 64;
    int kbase = blockIdx.z * 256;
    int t = threadIdx.x;
    int ni = t & 15, mi = t >> 4;
    float acc[4] = {0, 0, 0, 0};

    for (int k0 = kbase; k0 < kbase + 256; k0 += KT) {
        if (t < 128) {
            int lm = t >> 3, lk = t & 7;
            float4 v = *(const float4*)(gHid + (size_t)(m0 + lm) * (2 * SD) + k0 + lk * 4);
            As[lm][lk * 4 + 0] = v.x; As[lm][lk * 4 + 1] = v.y;
            As[lm][lk * 4 + 2] = v.z; As[lm][lk * 4 + 3] = v.w;
        }
        #pragma unroll
        for (int rep = 0; rep < 2; rep++) {
            int i = t + rep * 256;
            int k = i >> 4, nc = i & 15;
            float4 v = *(const float4*)(W2 + (size_t)(k0 + k) * SD + n0 + nc * 4);
            *(float4*)&Bs[k][nc * 4] = v;
        }
        __syncthreads();
        #pragma unroll 8
        for (int k = 0; k < KT; k++) {
            float a = As[mi][k];
            float4 bv4 = *(const float4*)&Bs[k][ni * 4];
            acc[0] += a * bv4.x; acc[1] += a * bv4.y;
            acc[2] += a * bv4.z; acc[3] += a * bv4.w;
        }
        __syncthreads();
    }
    int m = m0 + mi;
    #pragma unroll
    for (int u = 0; u < 4; u++) {
        int n = n0 + ni * 4 + u;
        atomicAdd(&out[(size_t)m * SD + n], acc[u]);
    }
}

// ---------------------------------------------------------------------------
extern "C" void kernel_launch(void* const* d_in, const int* in_sizes, int n_in,
                              void* d_out, int out_size)
{
    const float* features = (const float*)d_in[0];
    const float* slots    = (const float*)d_in[1];
    const float* Wq   = (const float*)d_in[2];
    const float* bq   = (const float*)d_in[3];
    const float* Wk   = (const float*)d_in[4];
    const float* bk   = (const float*)d_in[5];
    const float* Wv   = (const float*)d_in[6];
    const float* bv   = (const float*)d_in[7];
    const float* W_ih = (const float*)d_in[8];
    const float* b_ih = (const float*)d_in[9];
    const float* W_hh = (const float*)d_in[10];
    const float* b_hh = (const float*)d_in[11];
    const float* g_pre  = (const float*)d_in[12];
    const float* b_pre  = (const float*)d_in[13];
    const float* g_post = (const float*)d_in[14];
    const float* b_post = (const float*)d_in[15];
    const float* W1 = (const float*)d_in[16];
    const float* b1 = (const float*)d_in[17];
    const float* W2 = (const float*)d_in[18];
    const float* b2 = (const float*)d_in[19];
    float* out = (float*)d_out;

    prep_kernel<<<BB * 2, 256>>>(slots, Wq, bq, Wk, bk, g_pre, b_pre);

    size_t smem = (size_t)(CC * FST + CC * NJ + NJ * AST) * sizeof(float);
    cudaFuncSetAttribute(main_kernel, cudaFuncAttributeMaxDynamicSharedMemorySize, (int)smem);
    main_kernel<<<dim3(NPIX / TILE_N, BB), 256, smem>>>(features);

    agg_kernel<<<BB * NH, 256>>>(Wv, bv);
    gru_kernel<<<dim3(NROWS / 64, SD / 32, 4), 256>>>(slots, W_ih, W_hh);
    fin_kernel<<<NROWS, 256>>>(slots, b_ih, b_hh, g_post, b_post, b2, out);
    mlp1_kernel<<<dim3(NROWS / 16, (2 * SD) / 64), 256>>>(W1, b1);
    mlp2_kernel<<<dim3(NROWS / 16, SD / 64, 2), 256>>>(W2, out);
}

// round 14
// speedup vs baseline: 1.4771x; 1.2649x over previous
#include <cuda_runtime.h>
#include <math.h>
#include <stdint.h>

// Problem constants
#define BB 32        // batch
#define CC 128       // FEAT_DIM
#define NPIX 4096    // H*W
#define SD 256       // SLOT_DIM
#define NS 8         // N_SLOTS
#define NH 4         // N_HEADS
#define HD 64        // HEAD_DIM
#define NJ 32        // NH*NS  (j = h*8 + s)
#define TILE_N 128
#define NROWS 256    // BB*NS flattened rows
#define FST 128      // featT smem row stride (XOR-swizzled chunks)
#define AST 132      // attn smem row stride (padded)
#define A2ST 40      // A2 smem row stride (conflict-free B-frag loads)
#define KT 32
#define RS (NROWS * SD)

// Scratch (device globals; no allocation allowed)
__device__ float gA[BB * CC * NJ];      // per-batch folded K-projection (128x32)
__device__ float gSbias[BB * NJ];       // score bias from bk
__device__ float gM[BB * NJ * CC];      // M[b][j][c]
__device__ float gSsum[BB * NJ];        // sum_n attn[b][j]
__device__ float gAgg[RS];              // agg (GRU input x), [row][dim]
__device__ float gLN[RS];               // post-LN of updated
__device__ float gHid[NROWS * 2 * SD];  // MLP hidden (post-ReLU)
__device__ float gPart[6 * RS];         // gRZ[256][512] | gIN[256][256] | gHN[256][256]

#define gRZ (gPart)
#define gIN (gPart + NROWS * 512)
#define gHN (gPart + NROWS * 512 + NROWS * 256)

// scalar read index into XOR-swizzled featT
__device__ __forceinline__ int fidx(int c, int n) {
    return c * FST + ((((n >> 2) ^ (c & 31))) << 2) + (n & 3);
}
__device__ __forceinline__ uint32_t to_tf32(float f) {
    uint32_t r;
    asm("cvt.rna.tf32.f32 %0, %1;" : "=r"(r) : "f"(f));
    return r;
}
__device__ __forceinline__ void mma168(float* d, uint32_t a0, uint32_t a1,
                                       uint32_t a2, uint32_t a3,
                                       uint32_t b0, uint32_t b1) {
    asm volatile(
        "mma.sync.aligned.m16n8k8.row.col.f32.tf32.tf32.f32 "
        "{%0,%1,%2,%3}, {%4,%5,%6,%7}, {%8,%9}, {%0,%1,%2,%3};"
        : "+f"(d[0]), "+f"(d[1]), "+f"(d[2]), "+f"(d[3])
        : "r"(a0), "r"(a1), "r"(a2), "r"(a3), "r"(b0), "r"(b1));
}

// ---------------------------------------------------------------------------
// Kernel 1: LN(slots) -> q(half) -> A fold for a head-pair. grid = BB*2 = 64.
// Also zeros gM, gSsum, and ALL of gPart.
// ---------------------------------------------------------------------------
__global__ void __launch_bounds__(256) prep_kernel(
    const float* __restrict__ slots,
    const float* __restrict__ Wq, const float* __restrict__ bq,
    const float* __restrict__ Wk, const float* __restrict__ bk,
    const float* __restrict__ g_pre, const float* __restrict__ b_pre)
{
    __shared__ float ln_s[NS][SD];
    __shared__ float qp[NS][128];
    __shared__ float q_s[NS][128];
    int b = blockIdx.x >> 1, hp = blockIdx.x & 1;
    int t = threadIdx.x;
    int w = t >> 5, lane = t & 31;

    for (int i = t; i < 16 * CC; i += 256)
        gM[b * NJ * CC + hp * 16 * CC + i] = 0.f;
    if (t < 16) gSsum[b * NJ + hp * 16 + t] = 0.f;
    {
        float4* z = (float4*)(gPart + (size_t)blockIdx.x * 6144);
        for (int i = t; i < 1536; i += 256) z[i] = make_float4(0.f, 0.f, 0.f, 0.f);
    }

    {
        const float* row = slots + (size_t)(b * NS + w) * SD;
        float s1 = 0.f, s2 = 0.f;
        for (int k = lane; k < SD; k += 32) { float v = row[k]; s1 += v; s2 += v * v; }
        #pragma unroll
        for (int o = 16; o; o >>= 1) {
            s1 += __shfl_xor_sync(0xffffffffu, s1, o);
            s2 += __shfl_xor_sync(0xffffffffu, s2, o);
        }
        float mu = s1 * (1.f / SD);
        float var = s2 * (1.f / SD) - mu * mu;
        float rs = rsqrtf(var + 1e-5f);
        for (int k = lane; k < SD; k += 32)
            ln_s[w][k] = (row[k] - mu) * rs * g_pre[k] + b_pre[k];
    }
    __syncthreads();

    {
        int dimL = t & 127, ks = t >> 7;
        int dim = hp * 128 + dimL;
        float acc[NS];
        #pragma unroll
        for (int s = 0; s < NS; s++) acc[s] = 0.f;
        int kb = ks * 128;
        #pragma unroll 8
        for (int k = kb; k < kb + 128; k++) {
            float wv = Wq[k * SD + dim];
            #pragma unroll
            for (int s = 0; s < NS; s++) acc[s] += ln_s[s][k] * wv;
        }
        if (ks == 1) {
            #pragma unroll
            for (int s = 0; s < NS; s++) qp[s][dimL] = acc[s];
        }
        __syncthreads();
        if (ks == 0) {
            float bqv = bq[dim];
            #pragma unroll
            for (int s = 0; s < NS; s++) q_s[s][dimL] = acc[s] + qp[s][dimL] + bqv;
        }
    }
    __syncthreads();

    const float scale = 0.125f;
    for (int idx = t; idx < CC * 16; idx += 256) {
        int c = idx >> 4, jl = idx & 15;
        int hl = jl >> 3, s = jl & 7;
        const float* wk = Wk + (size_t)c * SD + (2 * hp + hl) * HD;
        const float* qq = &q_s[s][hl * HD];
        float acc = 0.f;
        #pragma unroll 8
        for (int d = 0; d < HD; d++) acc += wk[d] * qq[d];
        gA[b * CC * NJ + c * NJ + hp * 16 + jl] = acc * scale;
    }
    if (t < 16) {
        int jl = t, hl = jl >> 3, s = jl & 7;
        float acc = 0.f;
        for (int d = 0; d < HD; d++)
            acc += bk[(2 * hp + hl) * HD + d] * q_s[s][hl * HD + d];
        gSbias[b * NJ + hp * 16 + jl] = acc * scale;
    }
}

// ---------------------------------------------------------------------------
// Kernel 2 (heavy): both GEMM phases on TF32 mma.sync; softmax in D-fragment.
// grid (32, 32).
// ---------------------------------------------------------------------------
__global__ void __launch_bounds__(256) main_kernel(const float* __restrict__ features)
{
    extern __shared__ uint32_t smu[];
    uint32_t* featT = smu;                  // [CC][FST] tf32 bits, swizzled
    uint32_t* A2    = featT + CC * FST;     // [CC][A2ST] tf32 bits
    uint32_t* attn  = A2 + CC * A2ST;       // [NJ][AST] tf32 bits

    int tile = blockIdx.x, b = blockIdx.y;
    int t = threadIdx.x;
    int wid = t >> 5, lane = t & 31;
    int n0 = tile * TILE_N;
    int row = lane >> 2, qd = lane & 3;

    // stage featT as tf32 bits
    const float* fb = features + (size_t)b * CC * NPIX + n0;
    for (int i = t; i < CC * TILE_N / 4; i += 256) {
        int c = i >> 5, n4 = i & 31;
        float4 v = ((const float4*)(fb + (size_t)c * NPIX))[n4];
        uint4 w = make_uint4(to_tf32(v.x), to_tf32(v.y), to_tf32(v.z), to_tf32(v.w));
        *(uint4*)&featT[c * FST + ((n4 ^ (c & 31)) << 2)] = w;
    }
    // stage A2 as tf32 bits (row stride 40)
    for (int i = t; i < CC * NJ / 4; i += 256) {
        int c = i >> 3, j4 = i & 7;
        float4 v = ((const float4*)(gA + b * CC * NJ))[i];
        uint4 w = make_uint4(to_tf32(v.x), to_tf32(v.y), to_tf32(v.z), to_tf32(v.w));
        *(uint4*)&A2[c * A2ST + j4 * 4] = w;
    }
    __syncthreads();

    // Phase 1: scores via MMA + fragment softmax. Warp wid owns pixels
    // [wid*16, wid*16+16). D[n16][j32] = featT^T @ A.
    {
        int nb0 = wid * 16;
        float d[4][4];
        #pragma unroll
        for (int jt = 0; jt < 4; jt++)
            #pragma unroll
            for (int u = 0; u < 4; u++) d[jt][u] = 0.f;

        #pragma unroll 4
        for (int kb = 0; kb < CC; kb += 8) {
            uint32_t a0 = featT[fidx(kb + qd,     nb0 + row)];
            uint32_t a1 = featT[fidx(kb + qd,     nb0 + row + 8)];
            uint32_t a2 = featT[fidx(kb + qd + 4, nb0 + row)];
            uint32_t a3 = featT[fidx(kb + qd + 4, nb0 + row + 8)];
            #pragma unroll
            for (int jt = 0; jt < 4; jt++) {
                uint32_t b0 = A2[(kb + qd) * A2ST + jt * 8 + row];
                uint32_t b1 = A2[(kb + qd + 4) * A2ST + jt * 8 + row];
                mma168(d[jt], a0, a1, a2, a3, b0, b1);
            }
        }

        // bias + softmax over the 8 slots of head jt (one quad holds them)
        #pragma unroll
        for (int jt = 0; jt < 4; jt++) {
            int j0 = jt * 8 + 2 * qd;
            float sb0 = gSbias[b * NJ + j0];
            float sb1 = gSbias[b * NJ + j0 + 1];
            float v0 = d[jt][0] + sb0, v1 = d[jt][1] + sb1;
            float v2 = d[jt][2] + sb0, v3 = d[jt][3] + sb1;

            float mlo = fmaxf(v0, v1), mhi = fmaxf(v2, v3);
            mlo = fmaxf(mlo, __shfl_xor_sync(0xffffffffu, mlo, 1));
            mlo = fmaxf(mlo, __shfl_xor_sync(0xffffffffu, mlo, 2));
            mhi = fmaxf(mhi, __shfl_xor_sync(0xffffffffu, mhi, 1));
            mhi = fmaxf(mhi, __shfl_xor_sync(0xffffffffu, mhi, 2));

            float e0 = __expf(v0 - mlo), e1 = __expf(v1 - mlo);
            float e2 = __expf(v2 - mhi), e3 = __expf(v3 - mhi);
            float slo = e0 + e1, shi = e2 + e3;
            slo += __shfl_xor_sync(0xffffffffu, slo, 1);
            slo += __shfl_xor_sync(0xffffffffu, slo, 2);
            shi += __shfl_xor_sync(0xffffffffu, shi, 1);
            shi += __shfl_xor_sync(0xffffffffu, shi, 2);
            float ilo = 1.f / slo, ihi = 1.f / shi;
            e0 *= ilo; e1 *= ilo; e2 *= ihi; e3 *= ihi;

            // store attn as tf32 bits: [j][AST] layout (conflict-free)
            attn[j0 * AST + nb0 + row]           = to_tf32(e0);
            attn[(j0 + 1) * AST + nb0 + row]     = to_tf32(e1);
            attn[j0 * AST + nb0 + row + 8]       = to_tf32(e2);
            attn[(j0 + 1) * AST + nb0 + row + 8] = to_tf32(e3);

            // Ssum partials: sum over this warp's 16 pixels
            float p0 = e0 + e2, p1 = e1 + e3;
            p0 += __shfl_xor_sync(0xffffffffu, p0, 4);
            p0 += __shfl_xor_sync(0xffffffffu, p0, 8);
            p0 += __shfl_xor_sync(0xffffffffu, p0, 16);
            p1 += __shfl_xor_sync(0xffffffffu, p1, 4);
            p1 += __shfl_xor_sync(0xffffffffu, p1, 8);
            p1 += __shfl_xor_sync(0xffffffffu, p1, 16);
            if (row == 0) {
                atomicAdd(&gSsum[b * NJ + j0], p0);
                atomicAdd(&gSsum[b * NJ + j0 + 1], p1);
            }
        }
    }
    __syncthreads();

    // Phase 3: M[c][j] via MMA. Warp wid owns c rows [wid*16, wid*16+16).
    {
        int cb = wid * 16;
        float d[4][4];
        #pragma unroll
        for (int jt = 0; jt < 4; jt++)
            #pragma unroll
            for (int u = 0; u < 4; u++) d[jt][u] = 0.f;

        #pragma unroll 4
        for (int nb = 0; nb < TILE_N; nb += 8) {
            uint32_t a0 = featT[fidx(cb + row,     nb + qd)];
            uint32_t a1 = featT[fidx(cb + row + 8, nb + qd)];
            uint32_t a2 = featT[fidx(cb + row,     nb + qd + 4)];
            uint32_t a3 = featT[fidx(cb + row + 8, nb + qd + 4)];
            #pragma unroll
            for (int jt = 0; jt < 4; jt++) {
                int j = jt * 8 + row;
                uint32_t b0 = attn[j * AST + nb + qd];
                uint32_t b1 = attn[j * AST + nb + qd + 4];
                mma168(d[jt], a0, a1, a2, a3, b0, b1);
            }
        }

        float* gm = gM + b * NJ * CC;
        #pragma unroll
        for (int jt = 0; jt < 4; jt++) {
            int j0 = jt * 8 + 2 * qd;
            atomicAdd(&gm[j0 * CC + cb + row],           d[jt][0]);
            atomicAdd(&gm[(j0 + 1) * CC + cb + row],     d[jt][1]);
            atomicAdd(&gm[j0 * CC + cb + row + 8],       d[jt][2]);
            atomicAdd(&gm[(j0 + 1) * CC + cb + row + 8], d[jt][3]);
        }
    }
}

// ---------------------------------------------------------------------------
// Kernel 3: agg[row][dim] = M[b][j] @ Wv[:,dim] + Ssum*bv. Block per (b, head).
// ---------------------------------------------------------------------------
__global__ void __launch_bounds__(256) agg_kernel(
    const float* __restrict__ Wv, const float* __restrict__ bv)
{
    __shared__ float Ms[NS][CC];
    __shared__ float Wvs[CC][HD];
    int b = blockIdx.x >> 2, h = blockIdx.x & 3;
    int t = threadIdx.x;
    {
        int s = t >> 5, c4 = t & 31;
        ((float4*)&Ms[s][0])[c4] =
            ((const float4*)(gM + (size_t)b * NJ * CC + (h * 8 + s) * CC))[c4];
    }
    #pragma unroll
    for (int j = 0; j < 8; j++) {
        int i = t + j * 256;
        int c = i >> 4, d4 = i & 15;
        ((float4*)&Wvs[c][0])[d4] =
            ((const float4*)(Wv + (size_t)c * SD + h * HD))[d4];
    }
    __syncthreads();
    #pragma unroll
    for (int rep = 0; rep < 2; rep++) {
        int o = t + rep * 256;
        int s = o >> 6, d = o & 63;
        int j = h * 8 + s;
        float acc = gSsum[b * NJ + j] * bv[h * HD + d];
        #pragma unroll 8
        for (int c = 0; c < CC; c++) acc += Ms[s][c] * Wvs[c][d];
        gAgg[(size_t)(b * NS + s) * SD + h * HD + d] = acc;
    }
}

// ---------------------------------------------------------------------------
// Kernel 4: GRU gate GEMM. Tile 64m x 32d x 3 gates, K-split 2, phase-split 2.
// grid (4, 8, 4) = 128 blocks. Atomic into zero-primed gPart.
// ---------------------------------------------------------------------------
__global__ void __launch_bounds__(256) gru_kernel(
    const float* __restrict__ slots,
    const float* __restrict__ W_ih, const float* __restrict__ W_hh)
{
    __shared__ float As[64][KT + 1];
    __shared__ float Bs[3][32][KT + 1];
    int m0 = blockIdx.x * 64, dim0 = blockIdx.y * 32;
    int phase = blockIdx.z >> 1, kh = blockIdx.z & 1;
    int t = threadIdx.x;
    int di = t & 15, mi = t >> 4;

    float accg[3][4][2];
    #pragma unroll
    for (int g = 0; g < 3; g++)
        #pragma unroll
        for (int i = 0; i < 4; i++)
            #pragma unroll
            for (int j = 0; j < 2; j++) accg[g][i][j] = 0.f;

    int lk = t & 7;
    const float* Ag = phase ? slots : gAgg;
    const float* Wg = phase ? W_hh : W_ih;
    int kbase = kh * 128;

    for (int k0 = kbase; k0 < kbase + 128; k0 += KT) {
        #pragma unroll
        for (int rep = 0; rep < 2; rep++) {
            int idx = t + rep * 256;
            int rw = idx >> 3;
            float4 v = *(const float4*)(Ag + (size_t)(m0 + rw) * SD + k0 + lk * 4);
            As[rw][lk * 4 + 0] = v.x; As[rw][lk * 4 + 1] = v.y;
            As[rw][lk * 4 + 2] = v.z; As[rw][lk * 4 + 3] = v.w;
        }
        {
            int lm = t >> 3;
            #pragma unroll
            for (int g = 0; g < 3; g++) {
                float4 v = *(const float4*)(Wg + (size_t)(g * SD + dim0 + lm) * SD + k0 + lk * 4);
                Bs[g][lm][lk * 4 + 0] = v.x; Bs[g][lm][lk * 4 + 1] = v.y;
                Bs[g][lm][lk * 4 + 2] = v.z; Bs[g][lm][lk * 4 + 3] = v.w;
            }
        }
        __syncthreads();
        #pragma unroll 4
        for (int k = 0; k < KT; k++) {
            float a[4];
            #pragma unroll
            for (int i = 0; i < 4; i++) a[i] = As[mi * 4 + i][k];
            #pragma unroll
            for (int g = 0; g < 3; g++) {
                float b0 = Bs[g][di * 2 + 0][k];
                float b1 = Bs[g][di * 2 + 1][k];
                #pragma unroll
                for (int i = 0; i < 4; i++) {
                    accg[g][i][0] += a[i] * b0;
                    accg[g][i][1] += a[i] * b1;
                }
            }
        }
        __syncthreads();
    }

    float* dstN = phase ? gHN : gIN;
    #pragma unroll
    for (int i = 0; i < 4; i++) {
        int m = m0 + mi * 4 + i;
        #pragma unroll
        for (int j = 0; j < 2; j++) {
            int d = dim0 + di * 2 + j;
            atomicAdd(&gRZ[(size_t)m * 512 + d], accg[0][i][j]);
            atomicAdd(&gRZ[(size_t)m * 512 + 256 + d], accg[1][i][j]);
            atomicAdd(&dstN[(size_t)m * SD + d], accg[2][i][j]);
        }
    }
}

// ---------------------------------------------------------------------------
// Kernel 5: GRU nonlin + post-LN + prime out = upd + b2. One row per block.
// ---------------------------------------------------------------------------
__global__ void __launch_bounds__(256) fin_kernel(
    const float* __restrict__ slots,
    const float* __restrict__ b_ih, const float* __restrict__ b_hh,
    const float* __restrict__ g_post, const float* __restrict__ b_post,
    const float* __restrict__ b2, float* __restrict__ out)
{
    __shared__ float red[16];
    __shared__ float stat[2];
    int row = blockIdx.x;
    int d = threadIdx.x;
    size_t ro = (size_t)row * SD;

    float rz_r = gRZ[(size_t)row * 512 + d] + b_ih[d] + b_hh[d];
    float rz_z = gRZ[(size_t)row * 512 + 256 + d] + b_ih[SD + d] + b_hh[SD + d];
    float in_ = gIN[ro + d] + b_ih[2 * SD + d];
    float hn  = gHN[ro + d] + b_hh[2 * SD + d];
    float r = 1.f / (1.f + expf(-rz_r));
    float z = 1.f / (1.f + expf(-rz_z));
    float nn = tanhf(in_ + r * hn);
    float hp = slots[ro + d];
    float v = (1.f - z) * nn + z * hp;
    out[ro + d] = v + b2[d];

    float s1 = v, s2 = v * v;
    #pragma unroll
    for (int o = 16; o; o >>= 1) {
        s1 += __shfl_xor_sync(0xffffffffu, s1, o);
        s2 += __shfl_xor_sync(0xffffffffu, s2, o);
    }
    int w = d >> 5, lane = d & 31;
    if (lane == 0) { red[w] = s1; red[8 + w] = s2; }
    __syncthreads();
    if (d == 0) {
        float t1 = 0.f, t2 = 0.f;
        #pragma unroll
        for (int i = 0; i < 8; i++) { t1 += red[i]; t2 += red[8 + i]; }
        float mu = t1 * (1.f / SD);
        float var = t2 * (1.f / SD) - mu * mu;
        stat[0] = mu;
        stat[1] = rsqrtf(var + 1e-5f);
    }
    __syncthreads();
    gLN[ro + d] = (v - stat[0]) * stat[1] * g_post[d] + b_post[d];
}

// ---------------------------------------------------------------------------
// Kernel 6: gHid = relu(gLN @ W1 + b1). Grid (16, 8) = 128, tile 16x64.
// ---------------------------------------------------------------------------
__global__ void __launch_bounds__(256) mlp1_kernel(
    const float* __restrict__ W1, const float* __restrict__ b1)
{
    __shared__ float As[16][KT + 1];
    __shared__ float Bs[KT][68];
    int m0 = blockIdx.x * 16, n0 = blockIdx.y * 64;
    int t = threadIdx.x;
    int ni = t & 15, mi = t >> 4;
    float acc[4] = {0, 0, 0, 0};

    for (int k0 = 0; k0 < SD; k0 += KT) {
        if (t < 128) {
            int lm = t >> 3, lk = t & 7;
            float4 v = *(const float4*)(gLN + (size_t)(m0 + lm) * SD + k0 + lk * 4);
            As[lm][lk * 4 + 0] = v.x; As[lm][lk * 4 + 1] = v.y;
            As[lm][lk * 4 + 2] = v.z; As[lm][lk * 4 + 3] = v.w;
        }
        #pragma unroll
        for (int rep = 0; rep < 2; rep++) {
            int i = t + rep * 256;
            int k = i >> 4, nc = i & 15;
            float4 v = *(const float4*)(W1 + (size_t)(k0 + k) * (2 * SD) + n0 + nc * 4);
            *(float4*)&Bs[k][nc * 4] = v;
        }
        __syncthreads();
        #pragma unroll 8
        for (int k = 0; k < KT; k++) {
            float a = As[mi][k];
            float4 bv4 = *(const float4*)&Bs[k][ni * 4];
            acc[0] += a * bv4.x; acc[1] += a * bv4.y;
            acc[2] += a * bv4.z; acc[3] += a * bv4.w;
        }
        __syncthreads();
    }
    int m = m0 + mi;
    #pragma unroll
    for (int u = 0; u < 4; u++) {
        int n = n0 + ni * 4 + u;
        gHid[(size_t)m * (2 * SD) + n] = fmaxf(acc[u] + b1[n], 0.f);
    }
}

// ---------------------------------------------------------------------------
// Kernel 7: out += gHid @ W2, K-split 2 (atomic into primed out).
// Grid (16, 4, 2), tile 16m x 64n x K256.
// ---------------------------------------------------------------------------
__global__ void __launch_bounds__(256) mlp2_kernel(
    const float* __restrict__ W2, float* __restrict__ out)
{
    __shared__ float As[16][KT + 1];
    __shared__ float Bs[KT][68];
    int m0 = blockIdx.x * 16, n0 = blockIdx.y * 64;
    int kbase = blockIdx.z * 256;
    int t = threadIdx.x;
    int ni = t & 15, mi = t >> 4;
    float acc[4] = {0, 0, 0, 0};

    for (int k0 = kbase; k0 < kbase + 256; k0 += KT) {
        if (t < 128) {
            int lm = t >> 3, lk = t & 7;
            float4 v = *(const float4*)(gHid + (size_t)(m0 + lm) * (2 * SD) + k0 + lk * 4);
            As[lm][lk * 4 + 0] = v.x; As[lm][lk * 4 + 1] = v.y;
            As[lm][lk * 4 + 2] = v.z; As[lm][lk * 4 + 3] = v.w;
        }
        #pragma unroll
        for (int rep = 0; rep < 2; rep++) {
            int i = t + rep * 256;
            int k = i >> 4, nc = i & 15;
            float4 v = *(const float4*)(W2 + (size_t)(k0 + k) * SD + n0 + nc * 4);
            *(float4*)&Bs[k][nc * 4] = v;
        }
        __syncthreads();
        #pragma unroll 8
        for (int k = 0; k < KT; k++) {
            float a = As[mi][k];
            float4 bv4 = *(const float4*)&Bs[k][ni * 4];
            acc[0] += a * bv4.x; acc[1] += a * bv4.y;
            acc[2] += a * bv4.z; acc[3] += a * bv4.w;
        }
        __syncthreads();
    }
    int m = m0 + mi;
    #pragma unroll
    for (int u = 0; u < 4; u++) {
        int n = n0 + ni * 4 + u;
        atomicAdd(&out[(size_t)m * SD + n], acc[u]);
    }
}

// ---------------------------------------------------------------------------
extern "C" void kernel_launch(void* const* d_in, const int* in_sizes, int n_in,
                              void* d_out, int out_size)
{
    const float* features = (const float*)d_in[0];
    const float* slots    = (const float*)d_in[1];
    const float* Wq   = (const float*)d_in[2];
    const float* bq   = (const float*)d_in[3];
    const float* Wk   = (const float*)d_in[4];
    const float* bk   = (const float*)d_in[5];
    const float* Wv   = (const float*)d_in[6];
    const float* bv   = (const float*)d_in[7];
    const float* W_ih = (const float*)d_in[8];
    const float* b_ih = (const float*)d_in[9];
    const float* W_hh = (const float*)d_in[10];
    const float* b_hh = (const float*)d_in[11];
    const float* g_pre  = (const float*)d_in[12];
    const float* b_pre  = (const float*)d_in[13];
    const float* g_post = (const float*)d_in[14];
    const float* b_post = (const float*)d_in[15];
    const float* W1 = (const float*)d_in[16];
    const float* b1 = (const float*)d_in[17];
    const float* W2 = (const float*)d_in[18];
    const float* b2 = (const float*)d_in[19];
    float* out = (float*)d_out;

    prep_kernel<<<BB * 2, 256>>>(slots, Wq, bq, Wk, bk, g_pre, b_pre);

    size_t smem = (size_t)(CC * FST + CC * A2ST + NJ * AST) * 4;
    cudaFuncSetAttribute(main_kernel, cudaFuncAttributeMaxDynamicSharedMemorySize, (int)smem);
    main_kernel<<<dim3(NPIX / TILE_N, BB), 256, smem>>>(features);

    agg_kernel<<<BB * NH, 256>>>(Wv, bv);
    gru_kernel<<<dim3(NROWS / 64, SD / 32, 4), 256>>>(slots, W_ih, W_hh);
    fin_kernel<<<NROWS, 256>>>(slots, b_ih, b_hh, g_post, b_post, b2, out);
    mlp1_kernel<<<dim3(NROWS / 16, (2 * SD) / 64), 256>>>(W1, b1);
    mlp2_kernel<<<dim3(NROWS / 16, SD / 64, 2), 256>>>(W2, out);
}